// round 1
// baseline (speedup 1.0000x reference)
#include <cuda_runtime.h>
#include <math.h>

#define T 2048
#define D 1024
#define H 16
#define DH 64
#define DFF 4096
#define D3 3072

// ---------------- scratch (device globals; no allocation allowed) ----------
__device__ float g_qin[(size_t)T * D];
__device__ float g_wheads[(size_t)T * D3];
__device__ float g_rk[(size_t)T * D];
__device__ float g_scores[(size_t)H * T * T];   // scores -> probs in place
__device__ float g_attnvec[(size_t)T * D];
__device__ float g_x[(size_t)T * D];
__device__ float g_y[(size_t)T * D];
__device__ float g_ff[(size_t)T * DFF];

// ---------------- reductions ----------------
__device__ __forceinline__ float warpSum(float v) {
#pragma unroll
    for (int o = 16; o > 0; o >>= 1) v += __shfl_xor_sync(0xffffffffu, v, o);
    return v;
}
__device__ __forceinline__ float warpMax(float v) {
#pragma unroll
    for (int o = 16; o > 0; o >>= 1) v = fmaxf(v, __shfl_xor_sync(0xffffffffu, v, o));
    return v;
}

// ---------------- layernorm: one block per row of 1024 ----------------
__global__ void ln_kernel(const float* __restrict__ x, const float* __restrict__ g,
                          const float* __restrict__ b, float* __restrict__ out) {
    const int row = blockIdx.x;
    const int t = threadIdx.x;              // 256 threads
    const float* xr = x + (size_t)row * D;
    float v[4];
    float s = 0.f;
#pragma unroll
    for (int c = 0; c < 4; c++) { v[c] = xr[t + c * 256]; s += v[c]; }
    __shared__ float red1[8], red2[8];
    s = warpSum(s);
    if ((t & 31) == 0) red1[t >> 5] = s;
    __syncthreads();
    float tot = red1[0] + red1[1] + red1[2] + red1[3] + red1[4] + red1[5] + red1[6] + red1[7];
    const float mean = tot * (1.0f / D);
    float s2 = 0.f;
#pragma unroll
    for (int c = 0; c < 4; c++) { float d = v[c] - mean; s2 += d * d; }
    s2 = warpSum(s2);
    if ((t & 31) == 0) red2[t >> 5] = s2;
    __syncthreads();
    float var = (red2[0] + red2[1] + red2[2] + red2[3] + red2[4] + red2[5] + red2[6] + red2[7]) * (1.0f / D);
    const float inv = rsqrtf(var + 1e-5f);
    float* orow = out + (size_t)row * D;
#pragma unroll
    for (int c = 0; c < 4; c++) {
        int col = t + c * 256;
        orow[col] = (v[c] - mean) * inv * g[col] + b[col];
    }
}

// ---------------- generic SGEMM: C[M,N] = A[M,K] @ B[K,N] (+bias)(relu)(+res)
// 64x64 tile, BK=16, 16x16 threads, 4x4 per thread. M,N,K multiples of 64/16.
template <bool BIAS, bool RELU, bool RES>
__global__ void sgemm_kernel(const float* __restrict__ A, const float* __restrict__ B,
                             const float* __restrict__ bias, const float* __restrict__ Rm,
                             float* __restrict__ C, int M, int N, int K) {
    __shared__ float As[64][17];
    __shared__ float Bs[16][64];
    const int tx = threadIdx.x, ty = threadIdx.y;
    const int t = ty * 16 + tx;
    const int m0 = blockIdx.y * 64, n0 = blockIdx.x * 64;
    float acc[4][4] = {};
    for (int k0 = 0; k0 < K; k0 += 16) {
#pragma unroll
        for (int e = 0; e < 4; e++) {
            int idx = t + e * 256;
            int m = idx >> 4, k = idx & 15;
            As[m][k] = A[(size_t)(m0 + m) * K + k0 + k];
            int kb = idx >> 6, n = idx & 63;
            Bs[kb][n] = B[(size_t)(k0 + kb) * N + n0 + n];
        }
        __syncthreads();
#pragma unroll
        for (int kk = 0; kk < 16; kk++) {
            float a[4];
#pragma unroll
            for (int ii = 0; ii < 4; ii++) a[ii] = As[ty * 4 + ii][kk];
            float4 b4 = *(const float4*)&Bs[kk][tx * 4];
            float b[4] = {b4.x, b4.y, b4.z, b4.w};
#pragma unroll
            for (int ii = 0; ii < 4; ii++)
#pragma unroll
                for (int jj = 0; jj < 4; jj++)
                    acc[ii][jj] = fmaf(a[ii], b[jj], acc[ii][jj]);
        }
        __syncthreads();
    }
    const int n = n0 + tx * 4;
    float bv[4] = {0.f, 0.f, 0.f, 0.f};
    if (BIAS) { bv[0] = bias[n]; bv[1] = bias[n + 1]; bv[2] = bias[n + 2]; bv[3] = bias[n + 3]; }
#pragma unroll
    for (int ii = 0; ii < 4; ii++) {
        int m = m0 + ty * 4 + ii;
        float4 c;
        c.x = acc[ii][0]; c.y = acc[ii][1]; c.z = acc[ii][2]; c.w = acc[ii][3];
        if (BIAS) { c.x += bv[0]; c.y += bv[1]; c.z += bv[2]; c.w += bv[3]; }
        if (RELU) { c.x = fmaxf(c.x, 0.f); c.y = fmaxf(c.y, 0.f); c.z = fmaxf(c.z, 0.f); c.w = fmaxf(c.w, 0.f); }
        if (RES) {
            float4 r = *(const float4*)&Rm[(size_t)m * N + n];
            c.x += r.x; c.y += r.y; c.z += r.z; c.w += r.w;
        }
        *(float4*)&C[(size_t)m * N + n] = c;
    }
}

// ---------------- fused attention scores: (AC + BD)*scale per head --------
// BD[i,j] = (q_i + r_r_bias) . r_k[T-1-(i-j)]  (valid for j<=i; rest unused)
__global__ void scores_kernel(const float* __restrict__ wh, const float* __restrict__ rk,
                              const float* __restrict__ rwb, const float* __restrict__ rrb,
                              float* __restrict__ sc) {
    const int h = blockIdx.z;
    const int i0 = blockIdx.y * 64, j0 = blockIdx.x * 64;
    if (j0 > i0 + 63) return;  // fully masked tile: skip (never read downstream)
    __shared__ float Qw[64][17], Qr[64][17], Ks[64][17], Rs[128][17];
    const int tx = threadIdx.x, ty = threadIdx.y;
    const int t = ty * 16 + tx;
    const int mbase = T - 64 - i0 + j0;
    float AC[4][4] = {}, BD[4][4] = {};
#pragma unroll 1
    for (int k0 = 0; k0 < DH; k0 += 16) {
#pragma unroll
        for (int e = 0; e < 4; e++) {
            int idx = t + e * 256;
            int m = idx >> 4, k = idx & 15;
            float q = wh[(size_t)(i0 + m) * D3 + h * DH + k0 + k];
            float rb1 = rwb[h * DH + k0 + k];
            float rb2 = rrb[h * DH + k0 + k];
            Qw[m][k] = q + rb1;
            Qr[m][k] = q + rb2;
            Ks[m][k] = wh[(size_t)(j0 + m) * D3 + D + h * DH + k0 + k];
        }
#pragma unroll
        for (int e = 0; e < 8; e++) {
            int idx = t + e * 256;
            int r = idx >> 4, k = idx & 15;
            int m = mbase + r;
            Rs[r][k] = (m >= 0 && m < T) ? rk[(size_t)m * D + h * DH + k0 + k] : 0.f;
        }
        __syncthreads();
        const int base = 63 - ty * 4 + tx * 4;
#pragma unroll
        for (int kk = 0; kk < 16; kk++) {
            float a[4], a2[4], b[4], rv[7];
#pragma unroll
            for (int ii = 0; ii < 4; ii++) { a[ii] = Qw[ty * 4 + ii][kk]; a2[ii] = Qr[ty * 4 + ii][kk]; }
#pragma unroll
            for (int jj = 0; jj < 4; jj++) b[jj] = Ks[tx * 4 + jj][kk];
#pragma unroll
            for (int p = 0; p < 7; p++) rv[p] = Rs[base - 3 + p][kk];
#pragma unroll
            for (int ii = 0; ii < 4; ii++)
#pragma unroll
                for (int jj = 0; jj < 4; jj++) {
                    AC[ii][jj] = fmaf(a[ii], b[jj], AC[ii][jj]);
                    BD[ii][jj] = fmaf(a2[ii], rv[jj - ii + 3], BD[ii][jj]);
                }
        }
        __syncthreads();
    }
    const float scale = 0.125f;  // 1/sqrt(64)
#pragma unroll
    for (int ii = 0; ii < 4; ii++) {
        int i = i0 + ty * 4 + ii;
        float4 c;
        c.x = (AC[ii][0] + BD[ii][0]) * scale;
        c.y = (AC[ii][1] + BD[ii][1]) * scale;
        c.z = (AC[ii][2] + BD[ii][2]) * scale;
        c.w = (AC[ii][3] + BD[ii][3]) * scale;
        *(float4*)&sc[((size_t)h * T + i) * T + j0 + tx * 4] = c;
    }
}

// ---------------- causal softmax, in place over scores rows ---------------
// one block (256 threads) per (i, h); row length i+1; zero-fill up to next 64.
__global__ void softmax_kernel(float* __restrict__ sc) {
    const int i = blockIdx.x;
    const int h = blockIdx.y;
    float* row = sc + ((size_t)h * T + i) * T;
    const int t = threadIdx.x;
    const int n = i + 1;
    const int nup = (i & ~63) + 64;
    float v[8];
    float mx = -3.4e38f;
#pragma unroll
    for (int c = 0; c < 8; c++) {
        int j = t + c * 256;
        v[c] = (j < n) ? row[j] : -3.4e38f;
        mx = fmaxf(mx, v[c]);
    }
    __shared__ float red1[8], red2[8];
    mx = warpMax(mx);
    if ((t & 31) == 0) red1[t >> 5] = mx;
    __syncthreads();
    mx = fmaxf(fmaxf(fmaxf(red1[0], red1[1]), fmaxf(red1[2], red1[3])),
               fmaxf(fmaxf(red1[4], red1[5]), fmaxf(red1[6], red1[7])));
    float s = 0.f;
#pragma unroll
    for (int c = 0; c < 8; c++) {
        int j = t + c * 256;
        float e = (j < n) ? __expf(v[c] - mx) : 0.f;
        v[c] = e;
        s += e;
    }
    s = warpSum(s);
    if ((t & 31) == 0) red2[t >> 5] = s;
    __syncthreads();
    float tot = red2[0] + red2[1] + red2[2] + red2[3] + red2[4] + red2[5] + red2[6] + red2[7];
    float inv = 1.0f / tot;
#pragma unroll
    for (int c = 0; c < 8; c++) {
        int j = t + c * 256;
        if (j < n) row[j] = v[c] * inv;
        else if (j < nup) row[j] = 0.f;   // zero pad so PV can read whole tiles
    }
}

// ---------------- probs layout transform: [h][i][j] -> [i][j][h] (coalesced)
__global__ void probs_out_kernel(const float* __restrict__ sc, float* __restrict__ out) {
    const int i = blockIdx.y;
    const int j0 = blockIdx.x * 64;
    const int t = threadIdx.x;  // 256
    float* dst = out + ((size_t)i * T + j0) * H;
    const int nup = (i & ~63) + 64;
    if (j0 < nup) {
        __shared__ float sm[16][65];
#pragma unroll
        for (int e = 0; e < 4; e++) {
            int idx = t + e * 256;
            int hh = idx >> 6, j = idx & 63;
            sm[hh][j] = sc[((size_t)hh * T + i) * T + j0 + j];
        }
        __syncthreads();
#pragma unroll
        for (int e = 0; e < 4; e++) {
            int idx = t + e * 256;
            dst[idx] = sm[idx & 15][idx >> 4];
        }
    } else {
#pragma unroll
        for (int e = 0; e < 4; e++) dst[t + e * 256] = 0.f;
    }
}

// ---------------- PV: attn_vec[i, h*64+d] = sum_{j<i0+64} P[h][i][j]*V[j][h*64+d]
__global__ void pv_kernel(const float* __restrict__ probs, const float* __restrict__ wh,
                          float* __restrict__ av) {
    const int h = blockIdx.y;
    const int i0 = blockIdx.x * 64;
    __shared__ float Ps[64][17];
    __shared__ float Vs[16][64];
    const int tx = threadIdx.x, ty = threadIdx.y;
    const int t = ty * 16 + tx;
    float acc[4][4] = {};
    const int kmax = i0 + 64;  // causal: P is zero-padded beyond row's length
    for (int k0 = 0; k0 < kmax; k0 += 16) {
#pragma unroll
        for (int e = 0; e < 4; e++) {
            int idx = t + e * 256;
            int m = idx >> 4, k = idx & 15;
            Ps[m][k] = probs[((size_t)h * T + i0 + m) * T + k0 + k];
            int kb = idx >> 6, n = idx & 63;
            Vs[kb][n] = wh[(size_t)(k0 + kb) * D3 + 2 * D + h * DH + n];
        }
        __syncthreads();
#pragma unroll
        for (int kk = 0; kk < 16; kk++) {
            float a[4];
#pragma unroll
            for (int ii = 0; ii < 4; ii++) a[ii] = Ps[ty * 4 + ii][kk];
            float4 b4 = *(const float4*)&Vs[kk][tx * 4];
            float b[4] = {b4.x, b4.y, b4.z, b4.w};
#pragma unroll
            for (int ii = 0; ii < 4; ii++)
#pragma unroll
                for (int jj = 0; jj < 4; jj++)
                    acc[ii][jj] = fmaf(a[ii], b[jj], acc[ii][jj]);
        }
        __syncthreads();
    }
#pragma unroll
    for (int ii = 0; ii < 4; ii++) {
        int i = i0 + ty * 4 + ii;
        float4 c;
        c.x = acc[ii][0]; c.y = acc[ii][1]; c.z = acc[ii][2]; c.w = acc[ii][3];
        *(float4*)&av[(size_t)i * D + h * DH + tx * 4] = c;
    }
}

// ---------------- host launch ----------------
extern "C" void kernel_launch(void* const* d_in, const int* in_sizes, int n_in,
                              void* d_out, int out_size) {
    const float* input = (const float*)d_in[0];
    const float* pos   = (const float*)d_in[1];
    const float* rwb   = (const float*)d_in[2];
    const float* rrb   = (const float*)d_in[3];
    // d_in[4] = mask (causal triu) — computed analytically, not read
    const float* ln1g  = (const float*)d_in[5];
    const float* ln1b  = (const float*)d_in[6];
    const float* qkvw  = (const float*)d_in[7];
    const float* rw    = (const float*)d_in[8];
    const float* ow    = (const float*)d_in[9];
    const float* ln2g  = (const float*)d_in[10];
    const float* ln2b  = (const float*)d_in[11];
    const float* ffw1  = (const float*)d_in[12];
    const float* ffb1  = (const float*)d_in[13];
    const float* ffw2  = (const float*)d_in[14];
    const float* ffb2  = (const float*)d_in[15];
    float* out = (float*)d_out;

    float *qin, *wheads, *rk, *scores, *attnvec, *x, *y, *ff;
    cudaGetSymbolAddress((void**)&qin,     g_qin);
    cudaGetSymbolAddress((void**)&wheads,  g_wheads);
    cudaGetSymbolAddress((void**)&rk,      g_rk);
    cudaGetSymbolAddress((void**)&scores,  g_scores);
    cudaGetSymbolAddress((void**)&attnvec, g_attnvec);
    cudaGetSymbolAddress((void**)&x,       g_x);
    cudaGetSymbolAddress((void**)&y,       g_y);
    cudaGetSymbolAddress((void**)&ff,      g_ff);

    const dim3 thr(16, 16);

    // 1) LN1
    ln_kernel<<<T, 256>>>(input, ln1g, ln1b, qin);
    // 2) QKV projection: (T,D)@(D,3D)
    sgemm_kernel<false, false, false><<<dim3(D3 / 64, T / 64), thr>>>(qin, qkvw, nullptr, nullptr, wheads, T, D3, D);
    // 3) r_k = pos @ r_w : (T,D)@(D,D)
    sgemm_kernel<false, false, false><<<dim3(D / 64, T / 64), thr>>>(pos, rw, nullptr, nullptr, rk, T, D, D);
    // 4) scores = (AC + BD) * scale, per head, lower-triangular tiles only
    scores_kernel<<<dim3(T / 64, T / 64, H), thr>>>(wheads, rk, rwb, rrb, scores);
    // 5) causal softmax in place -> probs in [h][i][j] layout
    softmax_kernel<<<dim3(T, H), 256>>>(scores);
    // 6) write probs to output in (i, j, b, h) layout (with zeros for j>i)
    if ((long long)out_size >= (long long)T * D + (long long)H * T * T) {
        probs_out_kernel<<<dim3(T / 64, T), 256>>>(scores, out + (size_t)T * D);
    }
    // 7) attn_vec = P @ V per head
    pv_kernel<<<dim3(T / 64, H), thr>>>(scores, wheads, attnvec);
    // 8) attn_out = attn_vec @ o_w ; x = input + attn_out
    sgemm_kernel<false, false, true><<<dim3(D / 64, T / 64), thr>>>(attnvec, ow, nullptr, input, x, T, D, D);
    // 9) LN2
    ln_kernel<<<T, 256>>>(x, ln2g, ln2b, y);
    // 10) FF1 + bias + relu
    sgemm_kernel<true, true, false><<<dim3(DFF / 64, T / 64), thr>>>(y, ffw1, ffb1, nullptr, ff, T, DFF, D);
    // 11) FF2 + bias + residual -> final x into d_out[0 : T*D]
    sgemm_kernel<true, false, true><<<dim3(D / 64, T / 64), thr>>>(ff, ffw2, ffb2, x, out, T, D, DFF);
}

// round 3
// speedup vs baseline: 1.8623x; 1.8623x over previous
#include <cuda_runtime.h>
#include <cuda_bf16.h>
#include <math.h>
#include <stdint.h>

#define T 2048
#define D 1024
#define H 16
#define DH 64
#define DFF 4096
#define D3 3072

// ======================= scratch (device globals) =======================
__device__ float g_wheads[(size_t)T * D3];
__device__ float g_rk[(size_t)T * D];
__device__ float g_scores[(size_t)H * T * T];
__device__ float g_x[(size_t)T * D];

__device__ __nv_bfloat16 g_qin_h[(size_t)T * D],  g_qin_l[(size_t)T * D];
__device__ __nv_bfloat16 g_y_h[(size_t)T * D],    g_y_l[(size_t)T * D];
__device__ __nv_bfloat16 g_pos_h[(size_t)T * D],  g_pos_l[(size_t)T * D];
__device__ __nv_bfloat16 g_av_h[(size_t)T * D],   g_av_l[(size_t)T * D];
__device__ __nv_bfloat16 g_ff_h[(size_t)T * DFF], g_ff_l[(size_t)T * DFF];

__device__ __nv_bfloat16 g_qkvwT_h[(size_t)D3 * D],  g_qkvwT_l[(size_t)D3 * D];
__device__ __nv_bfloat16 g_rwT_h[(size_t)D * D],     g_rwT_l[(size_t)D * D];
__device__ __nv_bfloat16 g_owT_h[(size_t)D * D],     g_owT_l[(size_t)D * D];
__device__ __nv_bfloat16 g_w1T_h[(size_t)DFF * D],   g_w1T_l[(size_t)DFF * D];
__device__ __nv_bfloat16 g_w2T_h[(size_t)D * DFF],   g_w2T_l[(size_t)D * DFF];

// ======================= small utils =======================
__device__ __forceinline__ float warpSum(float v) {
#pragma unroll
    for (int o = 16; o > 0; o >>= 1) v += __shfl_xor_sync(0xffffffffu, v, o);
    return v;
}
__device__ __forceinline__ float warpMax(float v) {
#pragma unroll
    for (int o = 16; o > 0; o >>= 1) v = fmaxf(v, __shfl_xor_sync(0xffffffffu, v, o));
    return v;
}
__device__ __forceinline__ void split_store(float v, __nv_bfloat16* h, __nv_bfloat16* l, size_t idx) {
    __nv_bfloat16 hi = __float2bfloat16(v);
    h[idx] = hi;
    l[idx] = __float2bfloat16(v - __bfloat162float(hi));
}
__device__ __forceinline__ uint32_t smem_u32(const void* p) {
    uint32_t a;
    asm("{ .reg .u64 tmp; cvta.to.shared.u64 tmp, %1; cvt.u32.u64 %0, tmp; }" : "=r"(a) : "l"(p));
    return a;
}

// ======================= HMMA helpers =======================
__device__ __forceinline__ void ldsm_x4(uint32_t* r, uint32_t addr) {
    asm volatile("ldmatrix.sync.aligned.m8n8.x4.shared.b16 {%0,%1,%2,%3}, [%4];"
                 : "=r"(r[0]), "=r"(r[1]), "=r"(r[2]), "=r"(r[3]) : "r"(addr));
}
__device__ __forceinline__ void mma16816(float* c, const uint32_t* a, uint32_t b0, uint32_t b1) {
    asm volatile(
        "mma.sync.aligned.m16n8k16.row.col.f32.bf16.bf16.f32 "
        "{%0,%1,%2,%3}, {%4,%5,%6,%7}, {%8,%9}, {%0,%1,%2,%3};"
        : "+f"(c[0]), "+f"(c[1]), "+f"(c[2]), "+f"(c[3])
        : "r"(a[0]), "r"(a[1]), "r"(a[2]), "r"(a[3]), "r"(b0), "r"(b1));
}

// ======================= convert kernels =======================
__global__ void splitcvt_kernel(const float* __restrict__ x, __nv_bfloat16* __restrict__ h,
                                __nv_bfloat16* __restrict__ l, int n) {
    int i = (blockIdx.x * 256 + threadIdx.x) * 4;
    if (i >= n) return;
    float4 v = *(const float4*)(x + i);
    split_store(v.x, h, l, i + 0);
    split_store(v.y, h, l, i + 1);
    split_store(v.z, h, l, i + 2);
    split_store(v.w, h, l, i + 3);
}

// transpose + split: W [K,N] f32 -> WT hi/lo [N,K] bf16
__global__ void wconvT_kernel(const float* __restrict__ W, __nv_bfloat16* __restrict__ th,
                              __nv_bfloat16* __restrict__ tl, int K, int N) {
    __shared__ float sm[32][33];
    const int k0 = blockIdx.y * 32, n0 = blockIdx.x * 32;
    const int tx = threadIdx.x, ty = threadIdx.y;   // 32 x 8
#pragma unroll
    for (int i = 0; i < 4; i++)
        sm[ty + 8 * i][tx] = W[(size_t)(k0 + ty + 8 * i) * N + n0 + tx];
    __syncthreads();
#pragma unroll
    for (int i = 0; i < 4; i++) {
        float v = sm[tx][ty + 8 * i];
        size_t o = (size_t)(n0 + ty + 8 * i) * K + k0 + tx;
        split_store(v, th, tl, o);
    }
}

// ======================= layernorm (writes bf16 hi/lo) =======================
__global__ void ln_kernel(const float* __restrict__ x, const float* __restrict__ g,
                          const float* __restrict__ b, __nv_bfloat16* __restrict__ oh,
                          __nv_bfloat16* __restrict__ ol) {
    const int row = blockIdx.x;
    const int t = threadIdx.x;              // 256 threads
    const float* xr = x + (size_t)row * D;
    float v[4];
    float s = 0.f;
#pragma unroll
    for (int c = 0; c < 4; c++) { v[c] = xr[t + c * 256]; s += v[c]; }
    __shared__ float red1[8], red2[8];
    s = warpSum(s);
    if ((t & 31) == 0) red1[t >> 5] = s;
    __syncthreads();
    float tot = red1[0] + red1[1] + red1[2] + red1[3] + red1[4] + red1[5] + red1[6] + red1[7];
    const float mean = tot * (1.0f / D);
    float s2 = 0.f;
#pragma unroll
    for (int c = 0; c < 4; c++) { float d = v[c] - mean; s2 += d * d; }
    s2 = warpSum(s2);
    if ((t & 31) == 0) red2[t >> 5] = s2;
    __syncthreads();
    float var = (red2[0] + red2[1] + red2[2] + red2[3] + red2[4] + red2[5] + red2[6] + red2[7]) * (1.0f / D);
    const float inv = rsqrtf(var + 1e-5f);
#pragma unroll
    for (int c = 0; c < 4; c++) {
        int col = t + c * 256;
        float o = (v[c] - mean) * inv * g[col] + b[col];
        split_store(o, oh, ol, (size_t)row * D + col);
    }
}

// ======================= HMMA GEMM =======================
// C[M,N] = A[M,K] @ B^T (B stored [N,K]); A,B bf16 hi/lo (3-term split).
// Block: 256 thr (8 warps 4x2), tile 128x128, BK=64, double-buffered cp.async.
// EPI bits: 1=bias, 2=relu, 4=residual, 8=split-output.
#define BM 128
#define BN 128
#define BK 64
#define MMSTRIDE 72                       // bf16 per smem row (144B, ldmatrix conflict-free)
#define ARR_BYTES (128 * MMSTRIDE * 2)    // 18432
#define STAGE_BYTES (4 * ARR_BYTES)       // 73728
#define MM_SMEM (2 * STAGE_BYTES)         // 147456

__device__ __forceinline__ uint32_t faddr(uint32_t base, int row0, int kk, int lane) {
    return base + (uint32_t)(((row0 + (lane & 15)) * MMSTRIDE + kk * 16 + ((lane >> 4) << 3)) * 2);
}

__device__ __forceinline__ void mm_load_chunk(
    const __nv_bfloat16* __restrict__ Ah, const __nv_bfloat16* __restrict__ Al,
    const __nv_bfloat16* __restrict__ Bh, const __nv_bfloat16* __restrict__ Bl,
    int m0, int n0, int K, int t, uint32_t stage_base, int tid) {
    const size_t k0 = (size_t)t * BK;
#pragma unroll
    for (int e = 0; e < 16; e++) {
        int idx = e * 256 + tid;            // 0..4095
        int arr = idx >> 10;                // 0..3: Ah, Al, Bh, Bl
        int row = (idx >> 3) & 127;
        int ck  = idx & 7;
        const __nv_bfloat16* src;
        if (arr == 0)      src = Ah + (size_t)(m0 + row) * K + k0 + ck * 8;
        else if (arr == 1) src = Al + (size_t)(m0 + row) * K + k0 + ck * 8;
        else if (arr == 2) src = Bh + (size_t)(n0 + row) * K + k0 + ck * 8;
        else               src = Bl + (size_t)(n0 + row) * K + k0 + ck * 8;
        uint32_t dst = stage_base + (uint32_t)arr * ARR_BYTES + (uint32_t)(row * 144 + ck * 16);
        asm volatile("cp.async.cg.shared.global [%0], [%1], 16;"
                     :: "r"(dst), "l"(__cvta_generic_to_global(src)) : "memory");
    }
    asm volatile("cp.async.commit_group;" ::: "memory");
}

template <int EPI>
__global__ void __launch_bounds__(256, 1) mm_kernel(
    const __nv_bfloat16* __restrict__ Ah, const __nv_bfloat16* __restrict__ Al,
    const __nv_bfloat16* __restrict__ Bh, const __nv_bfloat16* __restrict__ Bl,
    const float* __restrict__ bias, const float* __restrict__ Rm,
    float* __restrict__ Cf, __nv_bfloat16* __restrict__ Ch, __nv_bfloat16* __restrict__ Cl,
    int M, int N, int K) {
    extern __shared__ char smem[];
    const uint32_t sbase = smem_u32(smem);
    const int tid = threadIdx.x;
    const int wid = tid >> 5, lane = tid & 31;
    const int m0 = blockIdx.y * BM, n0 = blockIdx.x * BN;
    const int mrow = (wid & 3) * 32;       // warp m offset in tile
    const int nrow = (wid >> 2) * 64;      // warp n offset in tile

    float c[2][8][4] = {};
    const int nch = K / BK;

    mm_load_chunk(Ah, Al, Bh, Bl, m0, n0, K, 0, sbase, tid);

    for (int t = 0; t < nch; t++) {
        asm volatile("cp.async.wait_group 0;" ::: "memory");
        __syncthreads();
        if (t + 1 < nch)
            mm_load_chunk(Ah, Al, Bh, Bl, m0, n0, K, t + 1, sbase + ((t + 1) & 1) * STAGE_BYTES, tid);
        const uint32_t sb = sbase + (t & 1) * STAGE_BYTES;
#pragma unroll
        for (int kk = 0; kk < 4; kk++) {
            uint32_t ah[2][4], al[2][4], bh[4][4], bl[4][4];
            ldsm_x4(ah[0], faddr(sb,                 mrow,      kk, lane));
            ldsm_x4(ah[1], faddr(sb,                 mrow + 16, kk, lane));
            ldsm_x4(al[0], faddr(sb + ARR_BYTES,     mrow,      kk, lane));
            ldsm_x4(al[1], faddr(sb + ARR_BYTES,     mrow + 16, kk, lane));
#pragma unroll
            for (int nf = 0; nf < 4; nf++)
                ldsm_x4(bh[nf], faddr(sb + 2 * ARR_BYTES, nrow + nf * 16, kk, lane));
#pragma unroll
            for (int nf = 0; nf < 4; nf++)
                ldsm_x4(bl[nf], faddr(sb + 3 * ARR_BYTES, nrow + nf * 16, kk, lane));
#pragma unroll
            for (int mi = 0; mi < 2; mi++)
#pragma unroll
                for (int nb = 0; nb < 8; nb++) {
                    const int nf = nb >> 1, o = nb & 1;
                    mma16816(c[mi][nb], ah[mi], bh[nf][o], bh[nf][2 + o]);
                    mma16816(c[mi][nb], ah[mi], bl[nf][o], bl[nf][2 + o]);
                    mma16816(c[mi][nb], al[mi], bh[nf][o], bh[nf][2 + o]);
                }
        }
    }

    // epilogue straight from registers
    const int tq = lane >> 2, tr = lane & 3;
#pragma unroll
    for (int mi = 0; mi < 2; mi++)
#pragma unroll
        for (int nb = 0; nb < 8; nb++)
#pragma unroll
            for (int hh = 0; hh < 2; hh++) {
                int gr = m0 + mrow + mi * 16 + tq + hh * 8;
                int gc = n0 + nrow + nb * 8 + tr * 2;
                float v0 = c[mi][nb][hh * 2 + 0];
                float v1 = c[mi][nb][hh * 2 + 1];
                if (EPI & 1) { v0 += bias[gc]; v1 += bias[gc + 1]; }
                if (EPI & 2) { v0 = fmaxf(v0, 0.f); v1 = fmaxf(v1, 0.f); }
                if (EPI & 4) {
                    float2 r = *(const float2*)&Rm[(size_t)gr * N + gc];
                    v0 += r.x; v1 += r.y;
                }
                if (EPI & 8) {
                    split_store(v0, Ch, Cl, (size_t)gr * N + gc);
                    split_store(v1, Ch, Cl, (size_t)gr * N + gc + 1);
                } else {
                    float2 o; o.x = v0; o.y = v1;
                    *(float2*)&Cf[(size_t)gr * N + gc] = o;
                }
            }
}

// ======================= attention scores (fp32 SIMT) =======================
__global__ void scores_kernel(const float* __restrict__ wh, const float* __restrict__ rk,
                              const float* __restrict__ rwb, const float* __restrict__ rrb,
                              float* __restrict__ sc) {
    const int h = blockIdx.z;
    const int i0 = blockIdx.y * 64, j0 = blockIdx.x * 64;
    if (j0 > i0 + 63) return;
    __shared__ float Qw[64][17], Qr[64][17], Ks[64][17], Rs[128][17];
    const int tx = threadIdx.x, ty = threadIdx.y;
    const int t = ty * 16 + tx;
    const int mbase = T - 64 - i0 + j0;
    float AC[4][4] = {}, BD[4][4] = {};
#pragma unroll 1
    for (int k0 = 0; k0 < DH; k0 += 16) {
#pragma unroll
        for (int e = 0; e < 4; e++) {
            int idx = t + e * 256;
            int m = idx >> 4, k = idx & 15;
            float q = wh[(size_t)(i0 + m) * D3 + h * DH + k0 + k];
            Qw[m][k] = q + rwb[h * DH + k0 + k];
            Qr[m][k] = q + rrb[h * DH + k0 + k];
            Ks[m][k] = wh[(size_t)(j0 + m) * D3 + D + h * DH + k0 + k];
        }
#pragma unroll
        for (int e = 0; e < 8; e++) {
            int idx = t + e * 256;
            int r = idx >> 4, k = idx & 15;
            int m = mbase + r;
            Rs[r][k] = (m >= 0 && m < T) ? rk[(size_t)m * D + h * DH + k0 + k] : 0.f;
        }
        __syncthreads();
        const int base = 63 - ty * 4 + tx * 4;
#pragma unroll
        for (int kk = 0; kk < 16; kk++) {
            float a[4], a2[4], b[4], rv[7];
#pragma unroll
            for (int ii = 0; ii < 4; ii++) { a[ii] = Qw[ty * 4 + ii][kk]; a2[ii] = Qr[ty * 4 + ii][kk]; }
#pragma unroll
            for (int jj = 0; jj < 4; jj++) b[jj] = Ks[tx * 4 + jj][kk];
#pragma unroll
            for (int p = 0; p < 7; p++) rv[p] = Rs[base - 3 + p][kk];
#pragma unroll
            for (int ii = 0; ii < 4; ii++)
#pragma unroll
                for (int jj = 0; jj < 4; jj++) {
                    AC[ii][jj] = fmaf(a[ii], b[jj], AC[ii][jj]);
                    BD[ii][jj] = fmaf(a2[ii], rv[jj - ii + 3], BD[ii][jj]);
                }
        }
        __syncthreads();
    }
    const float scale = 0.125f;
#pragma unroll
    for (int ii = 0; ii < 4; ii++) {
        int i = i0 + ty * 4 + ii;
        float4 c;
        c.x = (AC[ii][0] + BD[ii][0]) * scale;
        c.y = (AC[ii][1] + BD[ii][1]) * scale;
        c.z = (AC[ii][2] + BD[ii][2]) * scale;
        c.w = (AC[ii][3] + BD[ii][3]) * scale;
        *(float4*)&sc[((size_t)h * T + i) * T + j0 + tx * 4] = c;
    }
}

// ======================= causal softmax (in place) =======================
__global__ void softmax_kernel(float* __restrict__ sc) {
    const int i = blockIdx.x;
    const int h = blockIdx.y;
    float* row = sc + ((size_t)h * T + i) * T;
    const int t = threadIdx.x;
    const int n = i + 1;
    const int nup = (i & ~63) + 64;
    float v[8];
    float mx = -3.4e38f;
#pragma unroll
    for (int c = 0; c < 8; c++) {
        int j = t + c * 256;
        v[c] = (j < n) ? row[j] : -3.4e38f;
        mx = fmaxf(mx, v[c]);
    }
    __shared__ float red1[8], red2[8];
    mx = warpMax(mx);
    if ((t & 31) == 0) red1[t >> 5] = mx;
    __syncthreads();
    mx = fmaxf(fmaxf(fmaxf(red1[0], red1[1]), fmaxf(red1[2], red1[3])),
               fmaxf(fmaxf(red1[4], red1[5]), fmaxf(red1[6], red1[7])));
    float s = 0.f;
#pragma unroll
    for (int c = 0; c < 8; c++) {
        int j = t + c * 256;
        float e = (j < n) ? __expf(v[c] - mx) : 0.f;
        v[c] = e;
        s += e;
    }
    s = warpSum(s);
    if ((t & 31) == 0) red2[t >> 5] = s;
    __syncthreads();
    float tot = red2[0] + red2[1] + red2[2] + red2[3] + red2[4] + red2[5] + red2[6] + red2[7];
    float inv = 1.0f / tot;
#pragma unroll
    for (int c = 0; c < 8; c++) {
        int j = t + c * 256;
        if (j < n) row[j] = v[c] * inv;
        else if (j < nup) row[j] = 0.f;
    }
}

// ======================= probs layout: [h][i][j] -> [i][j][h] =======================
__global__ void probs_out_kernel(const float* __restrict__ sc, float* __restrict__ out) {
    const int i = blockIdx.y;
    const int j0 = blockIdx.x * 64;
    const int t = threadIdx.x;  // 256
    float* dst = out + ((size_t)i * T + j0) * H;
    const int nup = (i & ~63) + 64;
    if (j0 < nup) {
        __shared__ float sm[16][65];
#pragma unroll
        for (int e = 0; e < 4; e++) {
            int idx = t + e * 256;
            int hh = idx >> 6, j = idx & 63;
            sm[hh][j] = sc[((size_t)hh * T + i) * T + j0 + j];
        }
        __syncthreads();
#pragma unroll
        for (int e = 0; e < 4; e++) {
            int idx = t + e * 256;
            dst[idx] = sm[idx & 15][idx >> 4];
        }
    } else {
#pragma unroll
        for (int e = 0; e < 4; e++) dst[t + e * 256] = 0.f;
    }
}

// ======================= PV (writes attn_vec as bf16 hi/lo) =======================
__global__ void pv_kernel(const float* __restrict__ probs, const float* __restrict__ wh,
                          __nv_bfloat16* __restrict__ avh, __nv_bfloat16* __restrict__ avl) {
    const int h = blockIdx.y;
    const int i0 = blockIdx.x * 64;
    __shared__ float Ps[64][17];
    __shared__ float Vs[16][64];
    const int tx = threadIdx.x, ty = threadIdx.y;
    const int t = ty * 16 + tx;
    float acc[4][4] = {};
    const int kmax = i0 + 64;
    for (int k0 = 0; k0 < kmax; k0 += 16) {
#pragma unroll
        for (int e = 0; e < 4; e++) {
            int idx = t + e * 256;
            int m = idx >> 4, k = idx & 15;
            Ps[m][k] = probs[((size_t)h * T + i0 + m) * T + k0 + k];
            int kb = idx >> 6, n = idx & 63;
            Vs[kb][n] = wh[(size_t)(k0 + kb) * D3 + 2 * D + h * DH + n];
        }
        __syncthreads();
#pragma unroll
        for (int kk = 0; kk < 16; kk++) {
            float a[4];
#pragma unroll
            for (int ii = 0; ii < 4; ii++) a[ii] = Ps[ty * 4 + ii][kk];
            float4 b4 = *(const float4*)&Vs[kk][tx * 4];
            float b[4] = {b4.x, b4.y, b4.z, b4.w};
#pragma unroll
            for (int ii = 0; ii < 4; ii++)
#pragma unroll
                for (int jj = 0; jj < 4; jj++)
                    acc[ii][jj] = fmaf(a[ii], b[jj], acc[ii][jj]);
        }
        __syncthreads();
    }
#pragma unroll
    for (int ii = 0; ii < 4; ii++) {
        int i = i0 + ty * 4 + ii;
        size_t base = (size_t)i * D + h * DH + tx * 4;
#pragma unroll
        for (int jj = 0; jj < 4; jj++) split_store(acc[ii][jj], avh, avl, base + jj);
    }
}

// ======================= host launch =======================
extern "C" void kernel_launch(void* const* d_in, const int* in_sizes, int n_in,
                              void* d_out, int out_size) {
    const float* input = (const float*)d_in[0];
    const float* pos   = (const float*)d_in[1];
    const float* rwb   = (const float*)d_in[2];
    const float* rrb   = (const float*)d_in[3];
    // d_in[4] = mask (causal) — analytic
    const float* ln1g  = (const float*)d_in[5];
    const float* ln1b  = (const float*)d_in[6];
    const float* qkvw  = (const float*)d_in[7];
    const float* rw    = (const float*)d_in[8];
    const float* ow    = (const float*)d_in[9];
    const float* ln2g  = (const float*)d_in[10];
    const float* ln2b  = (const float*)d_in[11];
    const float* ffw1  = (const float*)d_in[12];
    const float* ffb1  = (const float*)d_in[13];
    const float* ffw2  = (const float*)d_in[14];
    const float* ffb2  = (const float*)d_in[15];
    float* out = (float*)d_out;

    float *wheads, *rk, *scores, *x;
    cudaGetSymbolAddress((void**)&wheads, g_wheads);
    cudaGetSymbolAddress((void**)&rk,     g_rk);
    cudaGetSymbolAddress((void**)&scores, g_scores);
    cudaGetSymbolAddress((void**)&x,      g_x);
    __nv_bfloat16 *qin_h, *qin_l, *y_h, *y_l, *pos_h, *pos_l, *av_h, *av_l, *ff_h, *ff_l;
    cudaGetSymbolAddress((void**)&qin_h, g_qin_h); cudaGetSymbolAddress((void**)&qin_l, g_qin_l);
    cudaGetSymbolAddress((void**)&y_h,   g_y_h);   cudaGetSymbolAddress((void**)&y_l,   g_y_l);
    cudaGetSymbolAddress((void**)&pos_h, g_pos_h); cudaGetSymbolAddress((void**)&pos_l, g_pos_l);
    cudaGetSymbolAddress((void**)&av_h,  g_av_h);  cudaGetSymbolAddress((void**)&av_l,  g_av_l);
    cudaGetSymbolAddress((void**)&ff_h,  g_ff_h);  cudaGetSymbolAddress((void**)&ff_l,  g_ff_l);
    __nv_bfloat16 *qkvwT_h, *qkvwT_l, *rwT_h, *rwT_l, *owT_h, *owT_l, *w1T_h, *w1T_l, *w2T_h, *w2T_l;
    cudaGetSymbolAddress((void**)&qkvwT_h, g_qkvwT_h); cudaGetSymbolAddress((void**)&qkvwT_l, g_qkvwT_l);
    cudaGetSymbolAddress((void**)&rwT_h,   g_rwT_h);   cudaGetSymbolAddress((void**)&rwT_l,   g_rwT_l);
    cudaGetSymbolAddress((void**)&owT_h,   g_owT_h);   cudaGetSymbolAddress((void**)&owT_l,   g_owT_l);
    cudaGetSymbolAddress((void**)&w1T_h,   g_w1T_h);   cudaGetSymbolAddress((void**)&w1T_l,   g_w1T_l);
    cudaGetSymbolAddress((void**)&w2T_h,   g_w2T_h);   cudaGetSymbolAddress((void**)&w2T_l,   g_w2T_l);

    cudaFuncSetAttribute((const void*)mm_kernel<0>,  cudaFuncAttributeMaxDynamicSharedMemorySize, MM_SMEM);
    cudaFuncSetAttribute((const void*)mm_kernel<4>,  cudaFuncAttributeMaxDynamicSharedMemorySize, MM_SMEM);
    cudaFuncSetAttribute((const void*)mm_kernel<11>, cudaFuncAttributeMaxDynamicSharedMemorySize, MM_SMEM);
    cudaFuncSetAttribute((const void*)mm_kernel<5>,  cudaFuncAttributeMaxDynamicSharedMemorySize, MM_SMEM);

    const dim3 thr(16, 16);
    const dim3 wthr(32, 8);

    // weight transpose+split
    wconvT_kernel<<<dim3(D3 / 32, D / 32), wthr>>>(qkvw, qkvwT_h, qkvwT_l, D, D3);
    wconvT_kernel<<<dim3(D / 32,  D / 32), wthr>>>(rw,   rwT_h,   rwT_l,   D, D);
    wconvT_kernel<<<dim3(D / 32,  D / 32), wthr>>>(ow,   owT_h,   owT_l,   D, D);
    wconvT_kernel<<<dim3(DFF / 32, D / 32), wthr>>>(ffw1, w1T_h,  w1T_l,   D, DFF);
    wconvT_kernel<<<dim3(D / 32, DFF / 32), wthr>>>(ffw2, w2T_h,  w2T_l,   DFF, D);
    splitcvt_kernel<<<(T * D) / 1024, 256>>>(pos, pos_h, pos_l, T * D);

    // 1) LN1 -> qin hi/lo
    ln_kernel<<<T, 256>>>(input, ln1g, ln1b, qin_h, qin_l);
    // 2) QKV: (T,D)@(D,3D) -> wheads f32
    mm_kernel<0><<<dim3(D3 / 128, T / 128), 256, MM_SMEM>>>(
        qin_h, qin_l, qkvwT_h, qkvwT_l, nullptr, nullptr, wheads, nullptr, nullptr, T, D3, D);
    // 3) r_k = pos @ r_w -> f32
    mm_kernel<0><<<dim3(D / 128, T / 128), 256, MM_SMEM>>>(
        pos_h, pos_l, rwT_h, rwT_l, nullptr, nullptr, rk, nullptr, nullptr, T, D, D);
    // 4) scores
    scores_kernel<<<dim3(T / 64, T / 64, H), thr>>>(wheads, rk, rwb, rrb, scores);
    // 5) softmax
    softmax_kernel<<<dim3(T, H), 256>>>(scores);
    // 6) probs -> output (i,j,b,h)
    if ((long long)out_size >= (long long)T * D + (long long)H * T * T) {
        probs_out_kernel<<<dim3(T / 64, T), 256>>>(scores, out + (size_t)T * D);
    }
    // 7) attn_vec = P @ V -> bf16 hi/lo
    pv_kernel<<<dim3(T / 64, H), thr>>>(scores, wheads, av_h, av_l);
    // 8) x = input + attn_vec @ o_w
    mm_kernel<4><<<dim3(D / 128, T / 128), 256, MM_SMEM>>>(
        av_h, av_l, owT_h, owT_l, nullptr, input, x, nullptr, nullptr, T, D, D);
    // 9) LN2 -> y hi/lo
    ln_kernel<<<T, 256>>>(x, ln2g, ln2b, y_h, y_l);
    // 10) FF1: relu(y@W1 + b1) -> ff hi/lo
    mm_kernel<11><<<dim3(DFF / 128, T / 128), 256, MM_SMEM>>>(
        y_h, y_l, w1T_h, w1T_l, ffb1, nullptr, nullptr, ff_h, ff_l, T, DFF, D);
    // 11) out = ff@W2 + b2 + x
    mm_kernel<5><<<dim3(D / 128, T / 128), 256, MM_SMEM>>>(
        ff_h, ff_l, w2T_h, w2T_l, ffb2, x, out, nullptr, nullptr, T, D, DFF);
}

// round 4
// speedup vs baseline: 2.1936x; 1.1779x over previous
#include <cuda_runtime.h>
#include <cuda_bf16.h>
#include <math.h>
#include <stdint.h>

#define T 2048
#define D 1024
#define H 16
#define DH 64
#define DFF 4096
#define D3 3072

// ======================= scratch (device globals) =======================
__device__ float g_wheads[(size_t)T * D3];
__device__ float g_rk[(size_t)T * D];
__device__ float g_scores[(size_t)H * T * T];
__device__ float g_x[(size_t)T * D];

__device__ __nv_bfloat16 g_qin_h[(size_t)T * D],  g_qin_l[(size_t)T * D];
__device__ __nv_bfloat16 g_y_h[(size_t)T * D],    g_y_l[(size_t)T * D];
__device__ __nv_bfloat16 g_pos_h[(size_t)T * D],  g_pos_l[(size_t)T * D];
__device__ __nv_bfloat16 g_av_h[(size_t)T * D],   g_av_l[(size_t)T * D];
__device__ __nv_bfloat16 g_ff_h[(size_t)T * DFF], g_ff_l[(size_t)T * DFF];

__device__ __nv_bfloat16 g_qkvwT_h[(size_t)D3 * D],  g_qkvwT_l[(size_t)D3 * D];
__device__ __nv_bfloat16 g_rwT_h[(size_t)D * D],     g_rwT_l[(size_t)D * D];
__device__ __nv_bfloat16 g_owT_h[(size_t)D * D],     g_owT_l[(size_t)D * D];
__device__ __nv_bfloat16 g_w1T_h[(size_t)DFF * D],   g_w1T_l[(size_t)DFF * D];
__device__ __nv_bfloat16 g_w2T_h[(size_t)D * DFF],   g_w2T_l[(size_t)D * DFF];

__device__ __nv_bfloat16 g_ph[(size_t)H * T * T];   // probs hi
__device__ __nv_bfloat16 g_pl[(size_t)H * T * T];   // probs lo
__device__ __nv_bfloat16 g_vt_h[(size_t)D * T];     // V^T hi: [h*64+d][t]
__device__ __nv_bfloat16 g_vt_l[(size_t)D * T];

// ======================= small utils =======================
__device__ __forceinline__ float warpSum(float v) {
#pragma unroll
    for (int o = 16; o > 0; o >>= 1) v += __shfl_xor_sync(0xffffffffu, v, o);
    return v;
}
__device__ __forceinline__ float warpMax(float v) {
#pragma unroll
    for (int o = 16; o > 0; o >>= 1) v = fmaxf(v, __shfl_xor_sync(0xffffffffu, v, o));
    return v;
}
__device__ __forceinline__ void split_store(float v, __nv_bfloat16* h, __nv_bfloat16* l, size_t idx) {
    __nv_bfloat16 hi = __float2bfloat16(v);
    h[idx] = hi;
    l[idx] = __float2bfloat16(v - __bfloat162float(hi));
}
__device__ __forceinline__ void split2(float v, __nv_bfloat16& h, __nv_bfloat16& l) {
    h = __float2bfloat16(v);
    l = __float2bfloat16(v - __bfloat162float(h));
}
__device__ __forceinline__ uint32_t smem_u32(const void* p) {
    uint32_t a;
    asm("{ .reg .u64 tmp; cvta.to.shared.u64 tmp, %1; cvt.u32.u64 %0, tmp; }" : "=r"(a) : "l"(p));
    return a;
}

// ======================= HMMA helpers =======================
__device__ __forceinline__ void ldsm_x4(uint32_t* r, uint32_t addr) {
    asm volatile("ldmatrix.sync.aligned.m8n8.x4.shared.b16 {%0,%1,%2,%3}, [%4];"
                 : "=r"(r[0]), "=r"(r[1]), "=r"(r[2]), "=r"(r[3]) : "r"(addr));
}
__device__ __forceinline__ void mma16816(float* c, const uint32_t* a, uint32_t b0, uint32_t b1) {
    asm volatile(
        "mma.sync.aligned.m16n8k16.row.col.f32.bf16.bf16.f32 "
        "{%0,%1,%2,%3}, {%4,%5,%6,%7}, {%8,%9}, {%0,%1,%2,%3};"
        : "+f"(c[0]), "+f"(c[1]), "+f"(c[2]), "+f"(c[3])
        : "r"(a[0]), "r"(a[1]), "r"(a[2]), "r"(a[3]), "r"(b0), "r"(b1));
}
#define MMSTRIDE 72
__device__ __forceinline__ uint32_t faddr(uint32_t base, int row0, int kk, int lane) {
    return base + (uint32_t)(((row0 + (lane & 15)) * MMSTRIDE + kk * 16 + ((lane >> 4) << 3)) * 2);
}

// ======================= convert kernels =======================
__global__ void splitcvt_kernel(const float* __restrict__ x, __nv_bfloat16* __restrict__ h,
                                __nv_bfloat16* __restrict__ l, int n) {
    int i = (blockIdx.x * 256 + threadIdx.x) * 4;
    if (i >= n) return;
    float4 v = *(const float4*)(x + i);
    split_store(v.x, h, l, i + 0);
    split_store(v.y, h, l, i + 1);
    split_store(v.z, h, l, i + 2);
    split_store(v.w, h, l, i + 3);
}

// transpose + split: W [K,N] f32 -> WT hi/lo [N,K] bf16
__global__ void wconvT_kernel(const float* __restrict__ W, __nv_bfloat16* __restrict__ th,
                              __nv_bfloat16* __restrict__ tl, int K, int N) {
    __shared__ float sm[32][33];
    const int k0 = blockIdx.y * 32, n0 = blockIdx.x * 32;
    const int tx = threadIdx.x, ty = threadIdx.y;   // 32 x 8
#pragma unroll
    for (int i = 0; i < 4; i++)
        sm[ty + 8 * i][tx] = W[(size_t)(k0 + ty + 8 * i) * N + n0 + tx];
    __syncthreads();
#pragma unroll
    for (int i = 0; i < 4; i++) {
        float v = sm[tx][ty + 8 * i];
        size_t o = (size_t)(n0 + ty + 8 * i) * K + k0 + tx;
        split_store(v, th, tl, o);
    }
}

// V^T conversion: wheads V section [t][2D + c] f32 -> VT hi/lo [c][t]
__global__ void vconvT_kernel(const float* __restrict__ wh, __nv_bfloat16* __restrict__ th,
                              __nv_bfloat16* __restrict__ tl) {
    __shared__ float sm[32][33];
    const int t0 = blockIdx.x * 32, c0 = blockIdx.y * 32;
    const int tx = threadIdx.x, ty = threadIdx.y;   // 32 x 8
#pragma unroll
    for (int i = 0; i < 4; i++)
        sm[ty + 8 * i][tx] = wh[(size_t)(t0 + ty + 8 * i) * D3 + 2 * D + c0 + tx];
    __syncthreads();
#pragma unroll
    for (int i = 0; i < 4; i++) {
        float v = sm[tx][ty + 8 * i];
        size_t o = (size_t)(c0 + ty + 8 * i) * T + t0 + tx;
        split_store(v, th, tl, o);
    }
}

// ======================= layernorm (writes bf16 hi/lo) =======================
__global__ void ln_kernel(const float* __restrict__ x, const float* __restrict__ g,
                          const float* __restrict__ b, __nv_bfloat16* __restrict__ oh,
                          __nv_bfloat16* __restrict__ ol) {
    const int row = blockIdx.x;
    const int t = threadIdx.x;              // 256 threads
    const float* xr = x + (size_t)row * D;
    float v[4];
    float s = 0.f;
#pragma unroll
    for (int c = 0; c < 4; c++) { v[c] = xr[t + c * 256]; s += v[c]; }
    __shared__ float red1[8], red2[8];
    s = warpSum(s);
    if ((t & 31) == 0) red1[t >> 5] = s;
    __syncthreads();
    float tot = red1[0] + red1[1] + red1[2] + red1[3] + red1[4] + red1[5] + red1[6] + red1[7];
    const float mean = tot * (1.0f / D);
    float s2 = 0.f;
#pragma unroll
    for (int c = 0; c < 4; c++) { float d = v[c] - mean; s2 += d * d; }
    s2 = warpSum(s2);
    if ((t & 31) == 0) red2[t >> 5] = s2;
    __syncthreads();
    float var = (red2[0] + red2[1] + red2[2] + red2[3] + red2[4] + red2[5] + red2[6] + red2[7]) * (1.0f / D);
    const float inv = rsqrtf(var + 1e-5f);
#pragma unroll
    for (int c = 0; c < 4; c++) {
        int col = t + c * 256;
        float o = (v[c] - mean) * inv * g[col] + b[col];
        split_store(o, oh, ol, (size_t)row * D + col);
    }
}

// ======================= HMMA GEMM (dense projections) =======================
#define BM 128
#define BN 128
#define BK 64
#define ARR_BYTES (128 * MMSTRIDE * 2)    // 18432
#define STAGE_BYTES (4 * ARR_BYTES)       // 73728
#define MM_SMEM (2 * STAGE_BYTES)         // 147456

__device__ __forceinline__ void mm_load_chunk(
    const __nv_bfloat16* __restrict__ Ah, const __nv_bfloat16* __restrict__ Al,
    const __nv_bfloat16* __restrict__ Bh, const __nv_bfloat16* __restrict__ Bl,
    int m0, int n0, int K, int t, uint32_t stage_base, int tid) {
    const size_t k0 = (size_t)t * BK;
#pragma unroll
    for (int e = 0; e < 16; e++) {
        int idx = e * 256 + tid;
        int arr = idx >> 10;
        int row = (idx >> 3) & 127;
        int ck  = idx & 7;
        const __nv_bfloat16* src;
        if (arr == 0)      src = Ah + (size_t)(m0 + row) * K + k0 + ck * 8;
        else if (arr == 1) src = Al + (size_t)(m0 + row) * K + k0 + ck * 8;
        else if (arr == 2) src = Bh + (size_t)(n0 + row) * K + k0 + ck * 8;
        else               src = Bl + (size_t)(n0 + row) * K + k0 + ck * 8;
        uint32_t dst = stage_base + (uint32_t)arr * ARR_BYTES + (uint32_t)(row * 144 + ck * 16);
        asm volatile("cp.async.cg.shared.global [%0], [%1], 16;"
                     :: "r"(dst), "l"(__cvta_generic_to_global(src)) : "memory");
    }
    asm volatile("cp.async.commit_group;" ::: "memory");
}

template <int EPI>
__global__ void __launch_bounds__(256, 1) mm_kernel(
    const __nv_bfloat16* __restrict__ Ah, const __nv_bfloat16* __restrict__ Al,
    const __nv_bfloat16* __restrict__ Bh, const __nv_bfloat16* __restrict__ Bl,
    const float* __restrict__ bias, const float* __restrict__ Rm,
    float* __restrict__ Cf, __nv_bfloat16* __restrict__ Ch, __nv_bfloat16* __restrict__ Cl,
    int M, int N, int K) {
    extern __shared__ char smem[];
    const uint32_t sbase = smem_u32(smem);
    const int tid = threadIdx.x;
    const int wid = tid >> 5, lane = tid & 31;
    const int m0 = blockIdx.y * BM, n0 = blockIdx.x * BN;
    const int mrow = (wid & 3) * 32;
    const int nrow = (wid >> 2) * 64;

    float c[2][8][4] = {};
    const int nch = K / BK;

    mm_load_chunk(Ah, Al, Bh, Bl, m0, n0, K, 0, sbase, tid);

    for (int t = 0; t < nch; t++) {
        asm volatile("cp.async.wait_group 0;" ::: "memory");
        __syncthreads();
        if (t + 1 < nch)
            mm_load_chunk(Ah, Al, Bh, Bl, m0, n0, K, t + 1, sbase + ((t + 1) & 1) * STAGE_BYTES, tid);
        const uint32_t sb = sbase + (t & 1) * STAGE_BYTES;
#pragma unroll
        for (int kk = 0; kk < 4; kk++) {
            uint32_t ah[2][4], al[2][4], bh[4][4], bl[4][4];
            ldsm_x4(ah[0], faddr(sb,                 mrow,      kk, lane));
            ldsm_x4(ah[1], faddr(sb,                 mrow + 16, kk, lane));
            ldsm_x4(al[0], faddr(sb + ARR_BYTES,     mrow,      kk, lane));
            ldsm_x4(al[1], faddr(sb + ARR_BYTES,     mrow + 16, kk, lane));
#pragma unroll
            for (int nf = 0; nf < 4; nf++)
                ldsm_x4(bh[nf], faddr(sb + 2 * ARR_BYTES, nrow + nf * 16, kk, lane));
#pragma unroll
            for (int nf = 0; nf < 4; nf++)
                ldsm_x4(bl[nf], faddr(sb + 3 * ARR_BYTES, nrow + nf * 16, kk, lane));
#pragma unroll
            for (int mi = 0; mi < 2; mi++)
#pragma unroll
                for (int nb = 0; nb < 8; nb++) {
                    const int nf = nb >> 1, o = nb & 1;
                    mma16816(c[mi][nb], ah[mi], bh[nf][o], bh[nf][2 + o]);
                    mma16816(c[mi][nb], ah[mi], bl[nf][o], bl[nf][2 + o]);
                    mma16816(c[mi][nb], al[mi], bh[nf][o], bh[nf][2 + o]);
                }
        }
    }

    const int tq = lane >> 2, tr = lane & 3;
#pragma unroll
    for (int mi = 0; mi < 2; mi++)
#pragma unroll
        for (int nb = 0; nb < 8; nb++)
#pragma unroll
            for (int hh = 0; hh < 2; hh++) {
                int gr = m0 + mrow + mi * 16 + tq + hh * 8;
                int gc = n0 + nrow + nb * 8 + tr * 2;
                float v0 = c[mi][nb][hh * 2 + 0];
                float v1 = c[mi][nb][hh * 2 + 1];
                if (EPI & 1) { v0 += bias[gc]; v1 += bias[gc + 1]; }
                if (EPI & 2) { v0 = fmaxf(v0, 0.f); v1 = fmaxf(v1, 0.f); }
                if (EPI & 4) {
                    float2 r = *(const float2*)&Rm[(size_t)gr * N + gc];
                    v0 += r.x; v1 += r.y;
                }
                if (EPI & 8) {
                    split_store(v0, Ch, Cl, (size_t)gr * N + gc);
                    split_store(v1, Ch, Cl, (size_t)gr * N + gc + 1);
                } else {
                    float2 o; o.x = v0; o.y = v1;
                    *(float2*)&Cf[(size_t)gr * N + gc] = o;
                }
            }
}

// ======================= HMMA attention scores =======================
// Per (h, 128x128 lower-tri tile): AC = (Q+rwb)K^T via MMA; BD via band GEMM
// Qr @ Rband^T (128x256), staged to smem in two halves, diagonally gathered.
#define SA 18432                    // one 128x72 bf16 array
#define SC_QR   (4 * SA)            // Qr_h, Qr_l
#define SC_RB   (6 * SA)            // Rb_h, Rb_l (256 rows x 72 each = 36864)
#define SC_SMEM (6 * SA + 2 * 36864)  // 184320

__global__ void __launch_bounds__(256, 1) scores_mma_kernel(
    const float* __restrict__ wh, const float* __restrict__ rk,
    const float* __restrict__ rwb, const float* __restrict__ rrb,
    float* __restrict__ sc) {
    const int h = blockIdx.z;
    const int i0 = blockIdx.y * 128, j0 = blockIdx.x * 128;
    if (j0 > i0) return;
    extern __shared__ char smem[];
    const uint32_t sb = smem_u32(smem);
    const int tid = threadIdx.x;
    const int wid = tid >> 5, lane = tid & 31;
    const int mrow = (wid & 3) * 32;
    const int nrow = (wid >> 2) * 64;
    const int pbase = T - 1 - i0 + j0 - 127;

    __nv_bfloat16* s_qwh = (__nv_bfloat16*)(smem);
    __nv_bfloat16* s_qwl = (__nv_bfloat16*)(smem + SA);
    __nv_bfloat16* s_kh  = (__nv_bfloat16*)(smem + 2 * SA);
    __nv_bfloat16* s_kl  = (__nv_bfloat16*)(smem + 3 * SA);
    __nv_bfloat16* s_qrh = (__nv_bfloat16*)(smem + SC_QR);
    __nv_bfloat16* s_qrl = (__nv_bfloat16*)(smem + SC_QR + SA);
    __nv_bfloat16* s_rh  = (__nv_bfloat16*)(smem + SC_RB);
    __nv_bfloat16* s_rl  = (__nv_bfloat16*)(smem + SC_RB + 36864);
    float* bdbuf = (float*)(smem);      // 128 x 130 f32, overlaps Qw/K region

    // ---- load + split into smem
#pragma unroll 4
    for (int e = 0; e < 32; e++) {
        int idx = e * 256 + tid;
        int r = idx >> 6, k = idx & 63;
        float q = wh[(size_t)(i0 + r) * D3 + h * DH + k];
        int o = r * MMSTRIDE + k;
        split2(q + rwb[h * DH + k], s_qwh[o], s_qwl[o]);
        split2(q + rrb[h * DH + k], s_qrh[o], s_qrl[o]);
        float kv = wh[(size_t)(j0 + r) * D3 + D + h * DH + k];
        split2(kv, s_kh[o], s_kl[o]);
    }
#pragma unroll 4
    for (int e = 0; e < 64; e++) {
        int idx = e * 256 + tid;
        int r = idx >> 6, k = idx & 63;
        int p = pbase + r;
        float rv = (p >= 0 && p < T) ? rk[(size_t)p * D + h * DH + k] : 0.f;
        int o = r * MMSTRIDE + k;
        split2(rv, s_rh[o], s_rl[o]);
    }
    __syncthreads();

    const uint32_t bqwh = sb, bqwl = sb + SA, bkh = sb + 2 * SA, bkl = sb + 3 * SA;
    const uint32_t bqrh = sb + SC_QR, bqrl = sb + SC_QR + SA;
    const uint32_t brh = sb + SC_RB, brl = sb + SC_RB + 36864;

    float acc[2][8][4] = {};
    // ---- AC phase
#pragma unroll
    for (int kk = 0; kk < 4; kk++) {
        uint32_t ah[2][4], al[2][4], bh[4][4], bl[4][4];
        ldsm_x4(ah[0], faddr(bqwh, mrow,      kk, lane));
        ldsm_x4(ah[1], faddr(bqwh, mrow + 16, kk, lane));
        ldsm_x4(al[0], faddr(bqwl, mrow,      kk, lane));
        ldsm_x4(al[1], faddr(bqwl, mrow + 16, kk, lane));
#pragma unroll
        for (int nf = 0; nf < 4; nf++) ldsm_x4(bh[nf], faddr(bkh, nrow + nf * 16, kk, lane));
#pragma unroll
        for (int nf = 0; nf < 4; nf++) ldsm_x4(bl[nf], faddr(bkl, nrow + nf * 16, kk, lane));
#pragma unroll
        for (int mi = 0; mi < 2; mi++)
#pragma unroll
            for (int nb = 0; nb < 8; nb++) {
                const int nf = nb >> 1, o = nb & 1;
                mma16816(acc[mi][nb], ah[mi], bh[nf][o], bh[nf][2 + o]);
                mma16816(acc[mi][nb], ah[mi], bl[nf][o], bl[nf][2 + o]);
                mma16816(acc[mi][nb], al[mi], bh[nf][o], bh[nf][2 + o]);
            }
    }

    // ---- BD phase: two 128-col halves of the 256-wide band
    const int tq = lane >> 2, tr = lane & 3;
#pragma unroll 1
    for (int half = 0; half < 2; half++) {
        float c2[2][8][4] = {};
#pragma unroll
        for (int kk = 0; kk < 4; kk++) {
            uint32_t ah[2][4], al[2][4], bh[4][4], bl[4][4];
            ldsm_x4(ah[0], faddr(bqrh, mrow,      kk, lane));
            ldsm_x4(ah[1], faddr(bqrh, mrow + 16, kk, lane));
            ldsm_x4(al[0], faddr(bqrl, mrow,      kk, lane));
            ldsm_x4(al[1], faddr(bqrl, mrow + 16, kk, lane));
#pragma unroll
            for (int nf = 0; nf < 4; nf++)
                ldsm_x4(bh[nf], faddr(brh, half * 128 + nrow + nf * 16, kk, lane));
#pragma unroll
            for (int nf = 0; nf < 4; nf++)
                ldsm_x4(bl[nf], faddr(brl, half * 128 + nrow + nf * 16, kk, lane));
#pragma unroll
            for (int mi = 0; mi < 2; mi++)
#pragma unroll
                for (int nb = 0; nb < 8; nb++) {
                    const int nf = nb >> 1, o = nb & 1;
                    mma16816(c2[mi][nb], ah[mi], bh[nf][o], bh[nf][2 + o]);
                    mma16816(c2[mi][nb], ah[mi], bl[nf][o], bl[nf][2 + o]);
                    mma16816(c2[mi][nb], al[mi], bh[nf][o], bh[nf][2 + o]);
                }
        }
        __syncthreads();     // half 0: also guards Qw/K (AC reads) before overwrite
#pragma unroll
        for (int mi = 0; mi < 2; mi++)
#pragma unroll
            for (int nb = 0; nb < 8; nb++)
#pragma unroll
                for (int hh = 0; hh < 2; hh++) {
                    int di = mrow + mi * 16 + tq + hh * 8;
                    int dj = nrow + nb * 8 + tr * 2;
                    bdbuf[di * 130 + dj]     = c2[mi][nb][hh * 2 + 0];
                    bdbuf[di * 130 + dj + 1] = c2[mi][nb][hh * 2 + 1];
                }
        __syncthreads();
#pragma unroll
        for (int mi = 0; mi < 2; mi++)
#pragma unroll
            for (int nb = 0; nb < 8; nb++)
#pragma unroll
                for (int hh = 0; hh < 2; hh++) {
                    int di = mrow + mi * 16 + tq + hh * 8;
                    int dj = nrow + nb * 8 + tr * 2;
#pragma unroll
                    for (int cc = 0; cc < 2; cc++) {
                        int pl = 127 + (dj + cc) - di;
                        if ((pl >> 7) == half)
                            acc[mi][nb][hh * 2 + cc] += bdbuf[di * 130 + (pl & 127)];
                    }
                }
        __syncthreads();
    }

    // ---- epilogue
    const float scale = 0.125f;
#pragma unroll
    for (int mi = 0; mi < 2; mi++)
#pragma unroll
        for (int nb = 0; nb < 8; nb++)
#pragma unroll
            for (int hh = 0; hh < 2; hh++) {
                int gi = i0 + mrow + mi * 16 + tq + hh * 8;
                int gj = j0 + nrow + nb * 8 + tr * 2;
                float2 o;
                o.x = acc[mi][nb][hh * 2 + 0] * scale;
                o.y = acc[mi][nb][hh * 2 + 1] * scale;
                *(float2*)&sc[((size_t)h * T + gi) * T + gj] = o;
            }
}

// ======================= causal softmax (in place, + bf16 hi/lo probs) ===========
__global__ void softmax_kernel(float* __restrict__ sc, __nv_bfloat16* __restrict__ ph,
                               __nv_bfloat16* __restrict__ pl) {
    const int i = blockIdx.x;
    const int h = blockIdx.y;
    const size_t roff = ((size_t)h * T + i) * T;
    float* row = sc + roff;
    const int t = threadIdx.x;
    const int n = i + 1;
    const int nup = (i & ~63) + 64;
    float v[8];
    float mx = -3.4e38f;
#pragma unroll
    for (int c = 0; c < 8; c++) {
        int j = t + c * 256;
        v[c] = (j < n) ? row[j] : -3.4e38f;
        mx = fmaxf(mx, v[c]);
    }
    __shared__ float red1[8], red2[8];
    mx = warpMax(mx);
    if ((t & 31) == 0) red1[t >> 5] = mx;
    __syncthreads();
    mx = fmaxf(fmaxf(fmaxf(red1[0], red1[1]), fmaxf(red1[2], red1[3])),
               fmaxf(fmaxf(red1[4], red1[5]), fmaxf(red1[6], red1[7])));
    float s = 0.f;
#pragma unroll
    for (int c = 0; c < 8; c++) {
        int j = t + c * 256;
        float e = (j < n) ? __expf(v[c] - mx) : 0.f;
        v[c] = e;
        s += e;
    }
    s = warpSum(s);
    if ((t & 31) == 0) red2[t >> 5] = s;
    __syncthreads();
    float tot = red2[0] + red2[1] + red2[2] + red2[3] + red2[4] + red2[5] + red2[6] + red2[7];
    float inv = 1.0f / tot;
#pragma unroll
    for (int c = 0; c < 8; c++) {
        int j = t + c * 256;
        if (j < n) {
            float p = v[c] * inv;
            row[j] = p;
            split_store(p, ph, pl, roff + j);
        } else if (j < nup) {
            row[j] = 0.f;
            ph[roff + j] = __float2bfloat16(0.f);
            pl[roff + j] = __float2bfloat16(0.f);
        }
    }
}

// ======================= probs layout: [h][i][j] -> [i][j][h] =======================
__global__ void probs_out_kernel(const float* __restrict__ sc, float* __restrict__ out) {
    const int i = blockIdx.y;
    const int j0 = blockIdx.x * 64;
    const int t = threadIdx.x;  // 256
    float* dst = out + ((size_t)i * T + j0) * H;
    const int nup = (i & ~63) + 64;
    if (j0 < nup) {
        __shared__ float sm[16][65];
#pragma unroll
        for (int e = 0; e < 4; e++) {
            int idx = t + e * 256;
            int hh = idx >> 6, j = idx & 63;
            sm[hh][j] = sc[((size_t)hh * T + i) * T + j0 + j];
        }
        __syncthreads();
#pragma unroll
        for (int e = 0; e < 4; e++) {
            int idx = t + e * 256;
            dst[idx] = sm[idx & 15][idx >> 4];
        }
    } else {
#pragma unroll
        for (int e = 0; e < 4; e++) dst[t + e * 256] = 0.f;
    }
}

// ======================= HMMA PV: attn_vec = P @ V =======================
// Block 128 thr (4 warps), tile 64(i) x 64(d), K = j chunks of 64, double-buffered.
#define PV_ARR (64 * MMSTRIDE * 2)     // 9216
#define PV_STAGE (4 * PV_ARR)          // 36864
#define PV_SMEM (2 * PV_STAGE)         // 73728

__device__ __forceinline__ void pv_load_chunk(
    const __nv_bfloat16* __restrict__ Ph, const __nv_bfloat16* __restrict__ Pl,
    const __nv_bfloat16* __restrict__ Vh, const __nv_bfloat16* __restrict__ Vl,
    int h, int i0, int t, uint32_t stage_base, int tid) {
    const size_t j0 = (size_t)t * 64;
#pragma unroll
    for (int e = 0; e < 16; e++) {
        int idx = e * 128 + tid;          // 0..2047
        int arr = idx >> 9;               // Ph, Pl, Vh, Vl
        int row = (idx >> 3) & 63;
        int ck  = idx & 7;
        const __nv_bfloat16* src;
        if (arr == 0)      src = Ph + ((size_t)h * T + i0 + row) * T + j0 + ck * 8;
        else if (arr == 1) src = Pl + ((size_t)h * T + i0 + row) * T + j0 + ck * 8;
        else if (arr == 2) src = Vh + (size_t)(h * DH + row) * T + j0 + ck * 8;
        else               src = Vl + (size_t)(h * DH + row) * T + j0 + ck * 8;
        uint32_t dst = stage_base + (uint32_t)arr * PV_ARR + (uint32_t)(row * 144 + ck * 16);
        asm volatile("cp.async.cg.shared.global [%0], [%1], 16;"
                     :: "r"(dst), "l"(__cvta_generic_to_global(src)) : "memory");
    }
    asm volatile("cp.async.commit_group;" ::: "memory");
}

__global__ void __launch_bounds__(128, 1) pv_mma_kernel(
    const __nv_bfloat16* __restrict__ Ph, const __nv_bfloat16* __restrict__ Pl,
    const __nv_bfloat16* __restrict__ Vh, const __nv_bfloat16* __restrict__ Vl,
    __nv_bfloat16* __restrict__ avh, __nv_bfloat16* __restrict__ avl) {
    extern __shared__ char smem[];
    const uint32_t sbase = smem_u32(smem);
    const int h = blockIdx.y;
    const int i0 = blockIdx.x * 64;
    const int tid = threadIdx.x;
    const int wid = tid >> 5, lane = tid & 31;
    const int mrow = wid * 16;

    float c[8][4] = {};
    const int nch = i0 / 64 + 1;

    pv_load_chunk(Ph, Pl, Vh, Vl, h, i0, 0, sbase, tid);

    for (int t = 0; t < nch; t++) {
        asm volatile("cp.async.wait_group 0;" ::: "memory");
        __syncthreads();
        if (t + 1 < nch)
            pv_load_chunk(Ph, Pl, Vh, Vl, h, i0, t + 1, sbase + ((t + 1) & 1) * PV_STAGE, tid);
        const uint32_t sb = sbase + (t & 1) * PV_STAGE;
#pragma unroll
        for (int kk = 0; kk < 4; kk++) {
            uint32_t ah[4], al[4], bh[4][4], bl[4][4];
            ldsm_x4(ah, faddr(sb,              mrow, kk, lane));
            ldsm_x4(al, faddr(sb + PV_ARR,     mrow, kk, lane));
#pragma unroll
            for (int nf = 0; nf < 4; nf++)
                ldsm_x4(bh[nf], faddr(sb + 2 * PV_ARR, nf * 16, kk, lane));
#pragma unroll
            for (int nf = 0; nf < 4; nf++)
                ldsm_x4(bl[nf], faddr(sb + 3 * PV_ARR, nf * 16, kk, lane));
#pragma unroll
            for (int nb = 0; nb < 8; nb++) {
                const int nf = nb >> 1, o = nb & 1;
                mma16816(c[nb], ah, bh[nf][o], bh[nf][2 + o]);
                mma16816(c[nb], ah, bl[nf][o], bl[nf][2 + o]);
                mma16816(c[nb], al, bh[nf][o], bh[nf][2 + o]);
            }
        }
    }

    const int tq = lane >> 2, tr = lane & 3;
#pragma unroll
    for (int nb = 0; nb < 8; nb++)
#pragma unroll
        for (int hh = 0; hh < 2; hh++) {
            int gi = i0 + mrow + tq + hh * 8;
            int gd = nb * 8 + tr * 2;
            size_t o = (size_t)gi * D + h * DH + gd;
            split_store(c[nb][hh * 2 + 0], avh, avl, o);
            split_store(c[nb][hh * 2 + 1], avh, avl, o + 1);
        }
}

// ======================= host launch =======================
extern "C" void kernel_launch(void* const* d_in, const int* in_sizes, int n_in,
                              void* d_out, int out_size) {
    const float* input = (const float*)d_in[0];
    const float* pos   = (const float*)d_in[1];
    const float* rwb   = (const float*)d_in[2];
    const float* rrb   = (const float*)d_in[3];
    // d_in[4] = mask (causal) — analytic
    const float* ln1g  = (const float*)d_in[5];
    const float* ln1b  = (const float*)d_in[6];
    const float* qkvw  = (const float*)d_in[7];
    const float* rw    = (const float*)d_in[8];
    const float* ow    = (const float*)d_in[9];
    const float* ln2g  = (const float*)d_in[10];
    const float* ln2b  = (const float*)d_in[11];
    const float* ffw1  = (const float*)d_in[12];
    const float* ffb1  = (const float*)d_in[13];
    const float* ffw2  = (const float*)d_in[14];
    const float* ffb2  = (const float*)d_in[15];
    float* out = (float*)d_out;

    float *wheads, *rk, *scores, *x;
    cudaGetSymbolAddress((void**)&wheads, g_wheads);
    cudaGetSymbolAddress((void**)&rk,     g_rk);
    cudaGetSymbolAddress((void**)&scores, g_scores);
    cudaGetSymbolAddress((void**)&x,      g_x);
    __nv_bfloat16 *qin_h, *qin_l, *y_h, *y_l, *pos_h, *pos_l, *av_h, *av_l, *ff_h, *ff_l;
    cudaGetSymbolAddress((void**)&qin_h, g_qin_h); cudaGetSymbolAddress((void**)&qin_l, g_qin_l);
    cudaGetSymbolAddress((void**)&y_h,   g_y_h);   cudaGetSymbolAddress((void**)&y_l,   g_y_l);
    cudaGetSymbolAddress((void**)&pos_h, g_pos_h); cudaGetSymbolAddress((void**)&pos_l, g_pos_l);
    cudaGetSymbolAddress((void**)&av_h,  g_av_h);  cudaGetSymbolAddress((void**)&av_l,  g_av_l);
    cudaGetSymbolAddress((void**)&ff_h,  g_ff_h);  cudaGetSymbolAddress((void**)&ff_l,  g_ff_l);
    __nv_bfloat16 *qkvwT_h, *qkvwT_l, *rwT_h, *rwT_l, *owT_h, *owT_l, *w1T_h, *w1T_l, *w2T_h, *w2T_l;
    cudaGetSymbolAddress((void**)&qkvwT_h, g_qkvwT_h); cudaGetSymbolAddress((void**)&qkvwT_l, g_qkvwT_l);
    cudaGetSymbolAddress((void**)&rwT_h,   g_rwT_h);   cudaGetSymbolAddress((void**)&rwT_l,   g_rwT_l);
    cudaGetSymbolAddress((void**)&owT_h,   g_owT_h);   cudaGetSymbolAddress((void**)&owT_l,   g_owT_l);
    cudaGetSymbolAddress((void**)&w1T_h,   g_w1T_h);   cudaGetSymbolAddress((void**)&w1T_l,   g_w1T_l);
    cudaGetSymbolAddress((void**)&w2T_h,   g_w2T_h);   cudaGetSymbolAddress((void**)&w2T_l,   g_w2T_l);
    __nv_bfloat16 *ph, *pl, *vt_h, *vt_l;
    cudaGetSymbolAddress((void**)&ph, g_ph);     cudaGetSymbolAddress((void**)&pl, g_pl);
    cudaGetSymbolAddress((void**)&vt_h, g_vt_h); cudaGetSymbolAddress((void**)&vt_l, g_vt_l);

    cudaFuncSetAttribute((const void*)mm_kernel<0>,  cudaFuncAttributeMaxDynamicSharedMemorySize, MM_SMEM);
    cudaFuncSetAttribute((const void*)mm_kernel<4>,  cudaFuncAttributeMaxDynamicSharedMemorySize, MM_SMEM);
    cudaFuncSetAttribute((const void*)mm_kernel<11>, cudaFuncAttributeMaxDynamicSharedMemorySize, MM_SMEM);
    cudaFuncSetAttribute((const void*)mm_kernel<5>,  cudaFuncAttributeMaxDynamicSharedMemorySize, MM_SMEM);
    cudaFuncSetAttribute((const void*)scores_mma_kernel, cudaFuncAttributeMaxDynamicSharedMemorySize, SC_SMEM);
    cudaFuncSetAttribute((const void*)pv_mma_kernel,  cudaFuncAttributeMaxDynamicSharedMemorySize, PV_SMEM);

    const dim3 wthr(32, 8);

    // weight transpose+split
    wconvT_kernel<<<dim3(D3 / 32, D / 32), wthr>>>(qkvw, qkvwT_h, qkvwT_l, D, D3);
    wconvT_kernel<<<dim3(D / 32,  D / 32), wthr>>>(rw,   rwT_h,   rwT_l,   D, D);
    wconvT_kernel<<<dim3(D / 32,  D / 32), wthr>>>(ow,   owT_h,   owT_l,   D, D);
    wconvT_kernel<<<dim3(DFF / 32, D / 32), wthr>>>(ffw1, w1T_h,  w1T_l,   D, DFF);
    wconvT_kernel<<<dim3(D / 32, DFF / 32), wthr>>>(ffw2, w2T_h,  w2T_l,   DFF, D);
    splitcvt_kernel<<<(T * D) / 1024, 256>>>(pos, pos_h, pos_l, T * D);

    // 1) LN1 -> qin hi/lo
    ln_kernel<<<T, 256>>>(input, ln1g, ln1b, qin_h, qin_l);
    // 2) QKV: (T,D)@(D,3D) -> wheads f32
    mm_kernel<0><<<dim3(D3 / 128, T / 128), 256, MM_SMEM>>>(
        qin_h, qin_l, qkvwT_h, qkvwT_l, nullptr, nullptr, wheads, nullptr, nullptr, T, D3, D);
    // 2b) V^T hi/lo for PV
    vconvT_kernel<<<dim3(T / 32, D / 32), wthr>>>(wheads, vt_h, vt_l);
    // 3) r_k = pos @ r_w -> f32
    mm_kernel<0><<<dim3(D / 128, T / 128), 256, MM_SMEM>>>(
        pos_h, pos_l, rwT_h, rwT_l, nullptr, nullptr, rk, nullptr, nullptr, T, D, D);
    // 4) scores via HMMA (AC + banded BD)
    scores_mma_kernel<<<dim3(T / 128, T / 128, H), 256, SC_SMEM>>>(wheads, rk, rwb, rrb, scores);
    // 5) softmax (also emits P hi/lo)
    softmax_kernel<<<dim3(T, H), 256>>>(scores, ph, pl);
    // 6) probs -> output (i,j,b,h)
    if ((long long)out_size >= (long long)T * D + (long long)H * T * T) {
        probs_out_kernel<<<dim3(T / 64, T), 256>>>(scores, out + (size_t)T * D);
    }
    // 7) attn_vec = P @ V via HMMA -> bf16 hi/lo
    pv_mma_kernel<<<dim3(T / 64, H), 128, PV_SMEM>>>(ph, pl, vt_h, vt_l, av_h, av_l);
    // 8) x = input + attn_vec @ o_w
    mm_kernel<4><<<dim3(D / 128, T / 128), 256, MM_SMEM>>>(
        av_h, av_l, owT_h, owT_l, nullptr, input, x, nullptr, nullptr, T, D, D);
    // 9) LN2 -> y hi/lo
    ln_kernel<<<T, 256>>>(x, ln2g, ln2b, y_h, y_l);
    // 10) FF1: relu(y@W1 + b1) -> ff hi/lo
    mm_kernel<11><<<dim3(DFF / 128, T / 128), 256, MM_SMEM>>>(
        y_h, y_l, w1T_h, w1T_l, ffb1, nullptr, nullptr, ff_h, ff_l, T, DFF, D);
    // 11) out = ff@W2 + b2 + x
    mm_kernel<5><<<dim3(D / 128, T / 128), 256, MM_SMEM>>>(
        ff_h, ff_l, w2T_h, w2T_l, ffb2, x, out, nullptr, nullptr, T, D, DFF);
}

// round 5
// speedup vs baseline: 2.3127x; 1.0543x over previous
#include <cuda_runtime.h>
#include <cuda_bf16.h>
#include <math.h>
#include <stdint.h>

#define T 2048
#define D 1024
#define H 16
#define DH 64
#define DFF 4096
#define D3 3072

// ======================= scratch (device globals) =======================
__device__ float g_wheads[(size_t)T * D3];
__device__ float g_rk[(size_t)T * D];
__device__ float g_scores[(size_t)H * T * T];
__device__ float g_x[(size_t)T * D];

__device__ __nv_bfloat16 g_qin_h[(size_t)T * D],  g_qin_l[(size_t)T * D];
__device__ __nv_bfloat16 g_y_h[(size_t)T * D],    g_y_l[(size_t)T * D];
__device__ __nv_bfloat16 g_pos_h[(size_t)T * D],  g_pos_l[(size_t)T * D];
__device__ __nv_bfloat16 g_av_h[(size_t)T * D],   g_av_l[(size_t)T * D];
__device__ __nv_bfloat16 g_ff_h[(size_t)T * DFF], g_ff_l[(size_t)T * DFF];

__device__ __nv_bfloat16 g_qkvwT_h[(size_t)D3 * D],  g_qkvwT_l[(size_t)D3 * D];
__device__ __nv_bfloat16 g_rwT_h[(size_t)D * D],     g_rwT_l[(size_t)D * D];
__device__ __nv_bfloat16 g_owT_h[(size_t)D * D],     g_owT_l[(size_t)D * D];
__device__ __nv_bfloat16 g_w1T_h[(size_t)DFF * D],   g_w1T_l[(size_t)DFF * D];
__device__ __nv_bfloat16 g_w2T_h[(size_t)D * DFF],   g_w2T_l[(size_t)D * DFF];

__device__ __nv_bfloat16 g_ph[(size_t)H * T * T];   // probs hi
__device__ __nv_bfloat16 g_pl[(size_t)H * T * T];   // probs lo
__device__ __nv_bfloat16 g_vt_h[(size_t)D * T];     // V^T hi: [h*64+d][t]
__device__ __nv_bfloat16 g_vt_l[(size_t)D * T];

// pre-split attention inputs
__device__ __nv_bfloat16 g_qw_h[(size_t)T * D], g_qw_l[(size_t)T * D];   // Q + r_w_bias
__device__ __nv_bfloat16 g_qr_h[(size_t)T * D], g_qr_l[(size_t)T * D];   // Q + r_r_bias
__device__ __nv_bfloat16 g_k_h[(size_t)T * D],  g_k_l[(size_t)T * D];    // K
__device__ __nv_bfloat16 g_rk_h[(size_t)T * D], g_rk_l[(size_t)T * D];   // r_k

// ======================= small utils =======================
__device__ __forceinline__ float warpSum(float v) {
#pragma unroll
    for (int o = 16; o > 0; o >>= 1) v += __shfl_xor_sync(0xffffffffu, v, o);
    return v;
}
__device__ __forceinline__ float warpMax(float v) {
#pragma unroll
    for (int o = 16; o > 0; o >>= 1) v = fmaxf(v, __shfl_xor_sync(0xffffffffu, v, o));
    return v;
}
__device__ __forceinline__ void split_store(float v, __nv_bfloat16* h, __nv_bfloat16* l, size_t idx) {
    __nv_bfloat16 hi = __float2bfloat16(v);
    h[idx] = hi;
    l[idx] = __float2bfloat16(v - __bfloat162float(hi));
}
__device__ __forceinline__ uint32_t smem_u32(const void* p) {
    uint32_t a;
    asm("{ .reg .u64 tmp; cvta.to.shared.u64 tmp, %1; cvt.u32.u64 %0, tmp; }" : "=r"(a) : "l"(p));
    return a;
}

// ======================= HMMA helpers =======================
__device__ __forceinline__ void ldsm_x4(uint32_t* r, uint32_t addr) {
    asm volatile("ldmatrix.sync.aligned.m8n8.x4.shared.b16 {%0,%1,%2,%3}, [%4];"
                 : "=r"(r[0]), "=r"(r[1]), "=r"(r[2]), "=r"(r[3]) : "r"(addr));
}
__device__ __forceinline__ void mma16816(float* c, const uint32_t* a, uint32_t b0, uint32_t b1) {
    asm volatile(
        "mma.sync.aligned.m16n8k16.row.col.f32.bf16.bf16.f32 "
        "{%0,%1,%2,%3}, {%4,%5,%6,%7}, {%8,%9}, {%0,%1,%2,%3};"
        : "+f"(c[0]), "+f"(c[1]), "+f"(c[2]), "+f"(c[3])
        : "r"(a[0]), "r"(a[1]), "r"(a[2]), "r"(a[3]), "r"(b0), "r"(b1));
}
#define MMSTRIDE 72
__device__ __forceinline__ uint32_t faddr(uint32_t base, int row0, int kk, int lane) {
    return base + (uint32_t)(((row0 + (lane & 15)) * MMSTRIDE + kk * 16 + ((lane >> 4) << 3)) * 2);
}
__device__ __forceinline__ void cpa16(uint32_t dst, const void* src) {
    asm volatile("cp.async.cg.shared.global [%0], [%1], 16;"
                 :: "r"(dst), "l"(__cvta_generic_to_global(src)) : "memory");
}
__device__ __forceinline__ void cpa16z(uint32_t dst, const void* src, int bytes) {
    asm volatile("cp.async.cg.shared.global [%0], [%1], 16, %2;"
                 :: "r"(dst), "l"(__cvta_generic_to_global(src)), "r"(bytes) : "memory");
}

// ======================= convert kernels =======================
__global__ void splitcvt_kernel(const float* __restrict__ x, __nv_bfloat16* __restrict__ h,
                                __nv_bfloat16* __restrict__ l, int n) {
    int i = (blockIdx.x * 256 + threadIdx.x) * 4;
    if (i >= n) return;
    float4 v = *(const float4*)(x + i);
    split_store(v.x, h, l, i + 0);
    split_store(v.y, h, l, i + 1);
    split_store(v.z, h, l, i + 2);
    split_store(v.w, h, l, i + 3);
}

// attention input prep: Q+rwb, Q+rrb, K -> bf16 hi/lo
__global__ void attnprep_kernel(const float* __restrict__ wh,
                                const float* __restrict__ rwb, const float* __restrict__ rrb,
                                __nv_bfloat16* __restrict__ qwh, __nv_bfloat16* __restrict__ qwl,
                                __nv_bfloat16* __restrict__ qrh, __nv_bfloat16* __restrict__ qrl,
                                __nv_bfloat16* __restrict__ kh,  __nv_bfloat16* __restrict__ kl) {
    size_t i = ((size_t)blockIdx.x * 256 + threadIdx.x) * 4;
    int t = (int)(i >> 10), c = (int)(i & 1023);
    float4 q  = *(const float4*)&wh[(size_t)t * D3 + c];
    float4 kv = *(const float4*)&wh[(size_t)t * D3 + D + c];
    float4 rw = *(const float4*)&rwb[c];
    float4 rr = *(const float4*)&rrb[c];
    split_store(q.x + rw.x, qwh, qwl, i + 0); split_store(q.y + rw.y, qwh, qwl, i + 1);
    split_store(q.z + rw.z, qwh, qwl, i + 2); split_store(q.w + rw.w, qwh, qwl, i + 3);
    split_store(q.x + rr.x, qrh, qrl, i + 0); split_store(q.y + rr.y, qrh, qrl, i + 1);
    split_store(q.z + rr.z, qrh, qrl, i + 2); split_store(q.w + rr.w, qrh, qrl, i + 3);
    split_store(kv.x, kh, kl, i + 0); split_store(kv.y, kh, kl, i + 1);
    split_store(kv.z, kh, kl, i + 2); split_store(kv.w, kh, kl, i + 3);
}

// transpose + split: W [K,N] f32 -> WT hi/lo [N,K] bf16
__global__ void wconvT_kernel(const float* __restrict__ W, __nv_bfloat16* __restrict__ th,
                              __nv_bfloat16* __restrict__ tl, int K, int N) {
    __shared__ float sm[32][33];
    const int k0 = blockIdx.y * 32, n0 = blockIdx.x * 32;
    const int tx = threadIdx.x, ty = threadIdx.y;   // 32 x 8
#pragma unroll
    for (int i = 0; i < 4; i++)
        sm[ty + 8 * i][tx] = W[(size_t)(k0 + ty + 8 * i) * N + n0 + tx];
    __syncthreads();
#pragma unroll
    for (int i = 0; i < 4; i++) {
        float v = sm[tx][ty + 8 * i];
        size_t o = (size_t)(n0 + ty + 8 * i) * K + k0 + tx;
        split_store(v, th, tl, o);
    }
}

// V^T conversion: wheads V section [t][2D + c] f32 -> VT hi/lo [c][t]
__global__ void vconvT_kernel(const float* __restrict__ wh, __nv_bfloat16* __restrict__ th,
                              __nv_bfloat16* __restrict__ tl) {
    __shared__ float sm[32][33];
    const int t0 = blockIdx.x * 32, c0 = blockIdx.y * 32;
    const int tx = threadIdx.x, ty = threadIdx.y;   // 32 x 8
#pragma unroll
    for (int i = 0; i < 4; i++)
        sm[ty + 8 * i][tx] = wh[(size_t)(t0 + ty + 8 * i) * D3 + 2 * D + c0 + tx];
    __syncthreads();
#pragma unroll
    for (int i = 0; i < 4; i++) {
        float v = sm[tx][ty + 8 * i];
        size_t o = (size_t)(c0 + ty + 8 * i) * T + t0 + tx;
        split_store(v, th, tl, o);
    }
}

// ======================= layernorm (writes bf16 hi/lo) =======================
__global__ void ln_kernel(const float* __restrict__ x, const float* __restrict__ g,
                          const float* __restrict__ b, __nv_bfloat16* __restrict__ oh,
                          __nv_bfloat16* __restrict__ ol) {
    const int row = blockIdx.x;
    const int t = threadIdx.x;              // 256 threads
    const float* xr = x + (size_t)row * D;
    float v[4];
    float s = 0.f;
#pragma unroll
    for (int c = 0; c < 4; c++) { v[c] = xr[t + c * 256]; s += v[c]; }
    __shared__ float red1[8], red2[8];
    s = warpSum(s);
    if ((t & 31) == 0) red1[t >> 5] = s;
    __syncthreads();
    float tot = red1[0] + red1[1] + red1[2] + red1[3] + red1[4] + red1[5] + red1[6] + red1[7];
    const float mean = tot * (1.0f / D);
    float s2 = 0.f;
#pragma unroll
    for (int c = 0; c < 4; c++) { float d = v[c] - mean; s2 += d * d; }
    s2 = warpSum(s2);
    if ((t & 31) == 0) red2[t >> 5] = s2;
    __syncthreads();
    float var = (red2[0] + red2[1] + red2[2] + red2[3] + red2[4] + red2[5] + red2[6] + red2[7]) * (1.0f / D);
    const float inv = rsqrtf(var + 1e-5f);
#pragma unroll
    for (int c = 0; c < 4; c++) {
        int col = t + c * 256;
        float o = (v[c] - mean) * inv * g[col] + b[col];
        split_store(o, oh, ol, (size_t)row * D + col);
    }
}

// ======================= HMMA GEMM (dense projections) =======================
#define BM 128
#define BN 128
#define BK 64
#define ARR_BYTES (128 * MMSTRIDE * 2)    // 18432
#define STAGE_BYTES (4 * ARR_BYTES)       // 73728
#define MM_SMEM (2 * STAGE_BYTES)         // 147456

__device__ __forceinline__ void mm_load_chunk(
    const __nv_bfloat16* __restrict__ Ah, const __nv_bfloat16* __restrict__ Al,
    const __nv_bfloat16* __restrict__ Bh, const __nv_bfloat16* __restrict__ Bl,
    int m0, int n0, int K, int t, uint32_t stage_base, int tid) {
    const size_t k0 = (size_t)t * BK;
#pragma unroll
    for (int e = 0; e < 16; e++) {
        int idx = e * 256 + tid;
        int arr = idx >> 10;
        int row = (idx >> 3) & 127;
        int ck  = idx & 7;
        const __nv_bfloat16* src;
        if (arr == 0)      src = Ah + (size_t)(m0 + row) * K + k0 + ck * 8;
        else if (arr == 1) src = Al + (size_t)(m0 + row) * K + k0 + ck * 8;
        else if (arr == 2) src = Bh + (size_t)(n0 + row) * K + k0 + ck * 8;
        else               src = Bl + (size_t)(n0 + row) * K + k0 + ck * 8;
        uint32_t dst = stage_base + (uint32_t)arr * ARR_BYTES + (uint32_t)(row * 144 + ck * 16);
        cpa16(dst, src);
    }
    asm volatile("cp.async.commit_group;" ::: "memory");
}

template <int EPI>
__global__ void __launch_bounds__(256, 1) mm_kernel(
    const __nv_bfloat16* __restrict__ Ah, const __nv_bfloat16* __restrict__ Al,
    const __nv_bfloat16* __restrict__ Bh, const __nv_bfloat16* __restrict__ Bl,
    const float* __restrict__ bias, const float* __restrict__ Rm,
    float* __restrict__ Cf, __nv_bfloat16* __restrict__ Ch, __nv_bfloat16* __restrict__ Cl,
    int M, int N, int K) {
    extern __shared__ char smem[];
    const uint32_t sbase = smem_u32(smem);
    const int tid = threadIdx.x;
    const int wid = tid >> 5, lane = tid & 31;
    const int m0 = blockIdx.y * BM, n0 = blockIdx.x * BN;
    const int mrow = (wid & 3) * 32;
    const int nrow = (wid >> 2) * 64;

    float c[2][8][4] = {};
    const int nch = K / BK;

    mm_load_chunk(Ah, Al, Bh, Bl, m0, n0, K, 0, sbase, tid);

    for (int t = 0; t < nch; t++) {
        asm volatile("cp.async.wait_group 0;" ::: "memory");
        __syncthreads();
        if (t + 1 < nch)
            mm_load_chunk(Ah, Al, Bh, Bl, m0, n0, K, t + 1, sbase + ((t + 1) & 1) * STAGE_BYTES, tid);
        const uint32_t sb = sbase + (t & 1) * STAGE_BYTES;
#pragma unroll
        for (int kk = 0; kk < 4; kk++) {
            uint32_t ah[2][4], al[2][4], bh[4][4], bl[4][4];
            ldsm_x4(ah[0], faddr(sb,                 mrow,      kk, lane));
            ldsm_x4(ah[1], faddr(sb,                 mrow + 16, kk, lane));
            ldsm_x4(al[0], faddr(sb + ARR_BYTES,     mrow,      kk, lane));
            ldsm_x4(al[1], faddr(sb + ARR_BYTES,     mrow + 16, kk, lane));
#pragma unroll
            for (int nf = 0; nf < 4; nf++)
                ldsm_x4(bh[nf], faddr(sb + 2 * ARR_BYTES, nrow + nf * 16, kk, lane));
#pragma unroll
            for (int nf = 0; nf < 4; nf++)
                ldsm_x4(bl[nf], faddr(sb + 3 * ARR_BYTES, nrow + nf * 16, kk, lane));
#pragma unroll
            for (int mi = 0; mi < 2; mi++)
#pragma unroll
                for (int nb = 0; nb < 8; nb++) {
                    const int nf = nb >> 1, o = nb & 1;
                    mma16816(c[mi][nb], ah[mi], bh[nf][o], bh[nf][2 + o]);
                    mma16816(c[mi][nb], ah[mi], bl[nf][o], bl[nf][2 + o]);
                    mma16816(c[mi][nb], al[mi], bh[nf][o], bh[nf][2 + o]);
                }
        }
    }

    const int tq = lane >> 2, tr = lane & 3;
#pragma unroll
    for (int mi = 0; mi < 2; mi++)
#pragma unroll
        for (int nb = 0; nb < 8; nb++)
#pragma unroll
            for (int hh = 0; hh < 2; hh++) {
                int gr = m0 + mrow + mi * 16 + tq + hh * 8;
                int gc = n0 + nrow + nb * 8 + tr * 2;
                float v0 = c[mi][nb][hh * 2 + 0];
                float v1 = c[mi][nb][hh * 2 + 1];
                if (EPI & 1) { v0 += bias[gc]; v1 += bias[gc + 1]; }
                if (EPI & 2) { v0 = fmaxf(v0, 0.f); v1 = fmaxf(v1, 0.f); }
                if (EPI & 4) {
                    float2 r = *(const float2*)&Rm[(size_t)gr * N + gc];
                    v0 += r.x; v1 += r.y;
                }
                if (EPI & 8) {
                    split_store(v0, Ch, Cl, (size_t)gr * N + gc);
                    split_store(v1, Ch, Cl, (size_t)gr * N + gc + 1);
                } else {
                    float2 o; o.x = v0; o.y = v1;
                    *(float2*)&Cf[(size_t)gr * N + gc] = o;
                }
            }
}

// ======================= HMMA attention scores =======================
#define SA 18432                      // one 128x72 bf16 array
#define SC_RB   (6 * SA)              // band offset
#define SC_SMEM (6 * SA + 2 * 36864)  // 184320

__global__ void __launch_bounds__(256, 1) scores_mma_kernel(
    const __nv_bfloat16* __restrict__ qwh, const __nv_bfloat16* __restrict__ qwl,
    const __nv_bfloat16* __restrict__ qrh, const __nv_bfloat16* __restrict__ qrl,
    const __nv_bfloat16* __restrict__ kh,  const __nv_bfloat16* __restrict__ kl,
    const __nv_bfloat16* __restrict__ rkh, const __nv_bfloat16* __restrict__ rkl,
    float* __restrict__ sc) {
    const int h = blockIdx.z;
    const int i0 = blockIdx.y * 128, j0 = blockIdx.x * 128;
    if (j0 > i0) return;
    extern __shared__ char smem[];
    const uint32_t sb = smem_u32(smem);
    const int tid = threadIdx.x;
    const int wid = tid >> 5, lane = tid & 31;
    const int mrow = (wid & 3) * 32;
    const int nrow = (wid >> 2) * 64;
    const int pbase = T - 1 - i0 + j0 - 127;
    float* bdbuf = (float*)(smem);      // 128 x 130 f32, overlaps Qw/K region

    // arrays: 0:qwh 1:qwl 2:kh 3:kl 4:qrh 5:qrl
#pragma unroll
    for (int e = 0; e < 24; e++) {
        int idx = e * 256 + tid;
        int arr = idx >> 10;
        int row = (idx >> 3) & 127;
        int ck  = idx & 7;
        const __nv_bfloat16* src;
        int grow = ((arr == 2 || arr == 3) ? j0 : i0) + row;
        if (arr == 0) src = qwh; else if (arr == 1) src = qwl;
        else if (arr == 2) src = kh; else if (arr == 3) src = kl;
        else if (arr == 4) src = qrh; else src = qrl;
        cpa16(sb + (uint32_t)arr * SA + (uint32_t)(row * 144 + ck * 16),
              src + (size_t)grow * D + h * DH + ck * 8);
    }
#pragma unroll
    for (int e = 0; e < 16; e++) {
        int idx = e * 256 + tid;
        int arr = idx >> 11;            // 0: rkh, 1: rkl
        int row = (idx >> 3) & 255;
        int ck  = idx & 7;
        int p = pbase + row;
        bool valid = (p >= 0 && p < T);
        size_t off = valid ? ((size_t)p * D + h * DH + ck * 8) : 0;
        cpa16z(sb + SC_RB + (uint32_t)arr * 36864u + (uint32_t)(row * 144 + ck * 16),
               (arr == 0 ? rkh : rkl) + off, valid ? 16 : 0);
    }
    asm volatile("cp.async.commit_group;" ::: "memory");
    asm volatile("cp.async.wait_group 0;" ::: "memory");
    __syncthreads();

    const uint32_t bqwh = sb, bqwl = sb + SA, bkh = sb + 2 * SA, bkl = sb + 3 * SA;
    const uint32_t bqrh = sb + 4 * SA, bqrl = sb + 5 * SA;
    const uint32_t brh = sb + SC_RB, brl = sb + SC_RB + 36864;

    float acc[2][8][4] = {};
#pragma unroll
    for (int kk = 0; kk < 4; kk++) {
        uint32_t ah[2][4], al[2][4], bh[4][4], bl[4][4];
        ldsm_x4(ah[0], faddr(bqwh, mrow,      kk, lane));
        ldsm_x4(ah[1], faddr(bqwh, mrow + 16, kk, lane));
        ldsm_x4(al[0], faddr(bqwl, mrow,      kk, lane));
        ldsm_x4(al[1], faddr(bqwl, mrow + 16, kk, lane));
#pragma unroll
        for (int nf = 0; nf < 4; nf++) ldsm_x4(bh[nf], faddr(bkh, nrow + nf * 16, kk, lane));
#pragma unroll
        for (int nf = 0; nf < 4; nf++) ldsm_x4(bl[nf], faddr(bkl, nrow + nf * 16, kk, lane));
#pragma unroll
        for (int mi = 0; mi < 2; mi++)
#pragma unroll
            for (int nb = 0; nb < 8; nb++) {
                const int nf = nb >> 1, o = nb & 1;
                mma16816(acc[mi][nb], ah[mi], bh[nf][o], bh[nf][2 + o]);
                mma16816(acc[mi][nb], ah[mi], bl[nf][o], bl[nf][2 + o]);
                mma16816(acc[mi][nb], al[mi], bh[nf][o], bh[nf][2 + o]);
            }
    }

    const int tq = lane >> 2, tr = lane & 3;
#pragma unroll 1
    for (int half = 0; half < 2; half++) {
        float c2[2][8][4] = {};
#pragma unroll
        for (int kk = 0; kk < 4; kk++) {
            uint32_t ah[2][4], al[2][4], bh[4][4], bl[4][4];
            ldsm_x4(ah[0], faddr(bqrh, mrow,      kk, lane));
            ldsm_x4(ah[1], faddr(bqrh, mrow + 16, kk, lane));
            ldsm_x4(al[0], faddr(bqrl, mrow,      kk, lane));
            ldsm_x4(al[1], faddr(bqrl, mrow + 16, kk, lane));
#pragma unroll
            for (int nf = 0; nf < 4; nf++)
                ldsm_x4(bh[nf], faddr(brh, half * 128 + nrow + nf * 16, kk, lane));
#pragma unroll
            for (int nf = 0; nf < 4; nf++)
                ldsm_x4(bl[nf], faddr(brl, half * 128 + nrow + nf * 16, kk, lane));
#pragma unroll
            for (int mi = 0; mi < 2; mi++)
#pragma unroll
                for (int nb = 0; nb < 8; nb++) {
                    const int nf = nb >> 1, o = nb & 1;
                    mma16816(c2[mi][nb], ah[mi], bh[nf][o], bh[nf][2 + o]);
                    mma16816(c2[mi][nb], ah[mi], bl[nf][o], bl[nf][2 + o]);
                    mma16816(c2[mi][nb], al[mi], bh[nf][o], bh[nf][2 + o]);
                }
        }
        __syncthreads();
#pragma unroll
        for (int mi = 0; mi < 2; mi++)
#pragma unroll
            for (int nb = 0; nb < 8; nb++)
#pragma unroll
                for (int hh = 0; hh < 2; hh++) {
                    int di = mrow + mi * 16 + tq + hh * 8;
                    int dj = nrow + nb * 8 + tr * 2;
                    bdbuf[di * 130 + dj]     = c2[mi][nb][hh * 2 + 0];
                    bdbuf[di * 130 + dj + 1] = c2[mi][nb][hh * 2 + 1];
                }
        __syncthreads();
#pragma unroll
        for (int mi = 0; mi < 2; mi++)
#pragma unroll
            for (int nb = 0; nb < 8; nb++)
#pragma unroll
                for (int hh = 0; hh < 2; hh++) {
                    int di = mrow + mi * 16 + tq + hh * 8;
                    int dj = nrow + nb * 8 + tr * 2;
#pragma unroll
                    for (int cc = 0; cc < 2; cc++) {
                        int pl = 127 + (dj + cc) - di;
                        if ((pl >> 7) == half)
                            acc[mi][nb][hh * 2 + cc] += bdbuf[di * 130 + (pl & 127)];
                    }
                }
        __syncthreads();
    }

    const float scale = 0.125f;
#pragma unroll
    for (int mi = 0; mi < 2; mi++)
#pragma unroll
        for (int nb = 0; nb < 8; nb++)
#pragma unroll
            for (int hh = 0; hh < 2; hh++) {
                int gi = i0 + mrow + mi * 16 + tq + hh * 8;
                int gj = j0 + nrow + nb * 8 + tr * 2;
                float2 o;
                o.x = acc[mi][nb][hh * 2 + 0] * scale;
                o.y = acc[mi][nb][hh * 2 + 1] * scale;
                *(float2*)&sc[((size_t)h * T + gi) * T + gj] = o;
            }
}

// ======================= causal softmax -> bf16 hi/lo probs (pad to 128) =====
__global__ void softmax_kernel(const float* __restrict__ sc, __nv_bfloat16* __restrict__ ph,
                               __nv_bfloat16* __restrict__ pl) {
    const int i = blockIdx.x;
    const int h = blockIdx.y;
    const size_t roff = ((size_t)h * T + i) * T;
    const float* row = sc + roff;
    const int t = threadIdx.x;
    const int n = i + 1;
    const int nup = (i & ~127) + 128;
    float v[8];
    float mx = -3.4e38f;
#pragma unroll
    for (int c = 0; c < 8; c++) {
        int j = t + c * 256;
        v[c] = (j < n) ? row[j] : -3.4e38f;
        mx = fmaxf(mx, v[c]);
    }
    __shared__ float red1[8], red2[8];
    mx = warpMax(mx);
    if ((t & 31) == 0) red1[t >> 5] = mx;
    __syncthreads();
    mx = fmaxf(fmaxf(fmaxf(red1[0], red1[1]), fmaxf(red1[2], red1[3])),
               fmaxf(fmaxf(red1[4], red1[5]), fmaxf(red1[6], red1[7])));
    float s = 0.f;
#pragma unroll
    for (int c = 0; c < 8; c++) {
        int j = t + c * 256;
        float e = (j < n) ? __expf(v[c] - mx) : 0.f;
        v[c] = e;
        s += e;
    }
    s = warpSum(s);
    if ((t & 31) == 0) red2[t >> 5] = s;
    __syncthreads();
    float tot = red2[0] + red2[1] + red2[2] + red2[3] + red2[4] + red2[5] + red2[6] + red2[7];
    float inv = 1.0f / tot;
#pragma unroll
    for (int c = 0; c < 8; c++) {
        int j = t + c * 256;
        if (j < n) {
            split_store(v[c] * inv, ph, pl, roff + j);
        } else if (j < nup) {
            ph[roff + j] = __float2bfloat16(0.f);
            pl[roff + j] = __float2bfloat16(0.f);
        }
    }
}

// ======================= probs layout: hi/lo [h][i][j] -> f32 [i][j][h] ========
__global__ void probs_out_kernel(const __nv_bfloat16* __restrict__ ph,
                                 const __nv_bfloat16* __restrict__ pl,
                                 float* __restrict__ out) {
    const int i = blockIdx.y;
    const int j0 = blockIdx.x * 64;
    const int t = threadIdx.x;  // 256
    float* dst = out + ((size_t)i * T + j0) * H;
    const int nup = (i & ~63) + 64;
    if (j0 < nup) {
        __shared__ float sm[16][65];
#pragma unroll
        for (int e = 0; e < 4; e++) {
            int idx = t + e * 256;
            int hh = idx >> 6, j = idx & 63;
            size_t o = ((size_t)hh * T + i) * T + j0 + j;
            sm[hh][j] = __bfloat162float(ph[o]) + __bfloat162float(pl[o]);
        }
        __syncthreads();
#pragma unroll
        for (int e = 0; e < 4; e++) {
            int idx = t + e * 256;
            dst[idx] = sm[idx & 15][idx >> 4];
        }
    } else {
#pragma unroll
        for (int e = 0; e < 4; e++) dst[t + e * 256] = 0.f;
    }
}

// ======================= HMMA PV: attn_vec = P @ V (128-row tiles) ===========
#define PV_PARR 18432
#define PV_VARR 9216
#define PV_STAGE (2 * PV_PARR + 2 * PV_VARR)  // 55296
#define PV_SMEM (2 * PV_STAGE)                // 110592

__device__ __forceinline__ void pv_load_chunk(
    const __nv_bfloat16* __restrict__ Ph, const __nv_bfloat16* __restrict__ Pl,
    const __nv_bfloat16* __restrict__ Vh, const __nv_bfloat16* __restrict__ Vl,
    int h, int i0, int t, uint32_t stage_base, int tid) {
    const size_t j0 = (size_t)t * 64;
#pragma unroll
    for (int e = 0; e < 12; e++) {
        int idx = e * 256 + tid;          // 0..3071
        const __nv_bfloat16* src;
        uint32_t dst;
        if (idx < 2048) {
            int arr = idx >> 10;
            int row = (idx >> 3) & 127;
            int ck  = idx & 7;
            src = (arr == 0 ? Ph : Pl) + ((size_t)h * T + i0 + row) * T + j0 + ck * 8;
            dst = stage_base + (uint32_t)arr * PV_PARR + (uint32_t)(row * 144 + ck * 16);
        } else {
            int k = idx - 2048;
            int arr = k >> 9;
            int row = (k >> 3) & 63;
            int ck  = k & 7;
            src = (arr == 0 ? Vh : Vl) + (size_t)(h * DH + row) * T + j0 + ck * 8;
            dst = stage_base + 2 * PV_PARR + (uint32_t)arr * PV_VARR + (uint32_t)(row * 144 + ck * 16);
        }
        cpa16(dst, src);
    }
    asm volatile("cp.async.commit_group;" ::: "memory");
}

__global__ void __launch_bounds__(256, 1) pv_mma_kernel(
    const __nv_bfloat16* __restrict__ Ph, const __nv_bfloat16* __restrict__ Pl,
    const __nv_bfloat16* __restrict__ Vh, const __nv_bfloat16* __restrict__ Vl,
    __nv_bfloat16* __restrict__ avh, __nv_bfloat16* __restrict__ avl) {
    extern __shared__ char smem[];
    const uint32_t sbase = smem_u32(smem);
    const int h = blockIdx.y;
    const int i0 = blockIdx.x * 128;
    const int tid = threadIdx.x;
    const int wid = tid >> 5, lane = tid & 31;
    const int mrow = (wid & 3) * 32;
    const int nrow = (wid >> 2) * 32;

    float c[2][4][4] = {};
    const int nch = i0 / 64 + 2;

    pv_load_chunk(Ph, Pl, Vh, Vl, h, i0, 0, sbase, tid);

    for (int t = 0; t < nch; t++) {
        asm volatile("cp.async.wait_group 0;" ::: "memory");
        __syncthreads();
        if (t + 1 < nch)
            pv_load_chunk(Ph, Pl, Vh, Vl, h, i0, t + 1, sbase + ((t + 1) & 1) * PV_STAGE, tid);
        const uint32_t sb = sbase + (t & 1) * PV_STAGE;
        const uint32_t vb = sb + 2 * PV_PARR;
#pragma unroll
        for (int kk = 0; kk < 4; kk++) {
            uint32_t ah[2][4], al[2][4], bh[2][4], bl[2][4];
            ldsm_x4(ah[0], faddr(sb,           mrow,      kk, lane));
            ldsm_x4(ah[1], faddr(sb,           mrow + 16, kk, lane));
            ldsm_x4(al[0], faddr(sb + PV_PARR, mrow,      kk, lane));
            ldsm_x4(al[1], faddr(sb + PV_PARR, mrow + 16, kk, lane));
            ldsm_x4(bh[0], faddr(vb,           nrow,      kk, lane));
            ldsm_x4(bh[1], faddr(vb,           nrow + 16, kk, lane));
            ldsm_x4(bl[0], faddr(vb + PV_VARR, nrow,      kk, lane));
            ldsm_x4(bl[1], faddr(vb + PV_VARR, nrow + 16, kk, lane));
#pragma unroll
            for (int mi = 0; mi < 2; mi++)
#pragma unroll
                for (int nb = 0; nb < 4; nb++) {
                    const int nf = nb >> 1, o = nb & 1;
                    mma16816(c[mi][nb], ah[mi], bh[nf][o], bh[nf][2 + o]);
                    mma16816(c[mi][nb], ah[mi], bl[nf][o], bl[nf][2 + o]);
                    mma16816(c[mi][nb], al[mi], bh[nf][o], bh[nf][2 + o]);
                }
        }
    }

    const int tq = lane >> 2, tr = lane & 3;
#pragma unroll
    for (int mi = 0; mi < 2; mi++)
#pragma unroll
        for (int nb = 0; nb < 4; nb++)
#pragma unroll
            for (int hh = 0; hh < 2; hh++) {
                int gi = i0 + mrow + mi * 16 + tq + hh * 8;
                int gd = nrow + nb * 8 + tr * 2;
                size_t o = (size_t)gi * D + h * DH + gd;
                split_store(c[mi][nb][hh * 2 + 0], avh, avl, o);
                split_store(c[mi][nb][hh * 2 + 1], avh, avl, o + 1);
            }
}

// ======================= host launch =======================
extern "C" void kernel_launch(void* const* d_in, const int* in_sizes, int n_in,
                              void* d_out, int out_size) {
    const float* input = (const float*)d_in[0];
    const float* pos   = (const float*)d_in[1];
    const float* rwb   = (const float*)d_in[2];
    const float* rrb   = (const float*)d_in[3];
    const float* ln1g  = (const float*)d_in[5];
    const float* ln1b  = (const float*)d_in[6];
    const float* qkvw  = (const float*)d_in[7];
    const float* rw    = (const float*)d_in[8];
    const float* ow    = (const float*)d_in[9];
    const float* ln2g  = (const float*)d_in[10];
    const float* ln2b  = (const float*)d_in[11];
    const float* ffw1  = (const float*)d_in[12];
    const float* ffb1  = (const float*)d_in[13];
    const float* ffw2  = (const float*)d_in[14];
    const float* ffb2  = (const float*)d_in[15];
    float* out = (float*)d_out;

    float *wheads, *rk, *scores, *x;
    cudaGetSymbolAddress((void**)&wheads, g_wheads);
    cudaGetSymbolAddress((void**)&rk,     g_rk);
    cudaGetSymbolAddress((void**)&scores, g_scores);
    cudaGetSymbolAddress((void**)&x,      g_x);
    __nv_bfloat16 *qin_h, *qin_l, *y_h, *y_l, *pos_h, *pos_l, *av_h, *av_l, *ff_h, *ff_l;
    cudaGetSymbolAddress((void**)&qin_h, g_qin_h); cudaGetSymbolAddress((void**)&qin_l, g_qin_l);
    cudaGetSymbolAddress((void**)&y_h,   g_y_h);   cudaGetSymbolAddress((void**)&y_l,   g_y_l);
    cudaGetSymbolAddress((void**)&pos_h, g_pos_h); cudaGetSymbolAddress((void**)&pos_l, g_pos_l);
    cudaGetSymbolAddress((void**)&av_h,  g_av_h);  cudaGetSymbolAddress((void**)&av_l,  g_av_l);
    cudaGetSymbolAddress((void**)&ff_h,  g_ff_h);  cudaGetSymbolAddress((void**)&ff_l,  g_ff_l);
    __nv_bfloat16 *qkvwT_h, *qkvwT_l, *rwT_h, *rwT_l, *owT_h, *owT_l, *w1T_h, *w1T_l, *w2T_h, *w2T_l;
    cudaGetSymbolAddress((void**)&qkvwT_h, g_qkvwT_h); cudaGetSymbolAddress((void**)&qkvwT_l, g_qkvwT_l);
    cudaGetSymbolAddress((void**)&rwT_h,   g_rwT_h);   cudaGetSymbolAddress((void**)&rwT_l,   g_rwT_l);
    cudaGetSymbolAddress((void**)&owT_h,   g_owT_h);   cudaGetSymbolAddress((void**)&owT_l,   g_owT_l);
    cudaGetSymbolAddress((void**)&w1T_h,   g_w1T_h);   cudaGetSymbolAddress((void**)&w1T_l,   g_w1T_l);
    cudaGetSymbolAddress((void**)&w2T_h,   g_w2T_h);   cudaGetSymbolAddress((void**)&w2T_l,   g_w2T_l);
    __nv_bfloat16 *ph, *pl, *vt_h, *vt_l;
    cudaGetSymbolAddress((void**)&ph, g_ph);     cudaGetSymbolAddress((void**)&pl, g_pl);
    cudaGetSymbolAddress((void**)&vt_h, g_vt_h); cudaGetSymbolAddress((void**)&vt_l, g_vt_l);
    __nv_bfloat16 *qw_h, *qw_l, *qr_h, *qr_l, *k_h, *k_l, *rk_h, *rk_l;
    cudaGetSymbolAddress((void**)&qw_h, g_qw_h); cudaGetSymbolAddress((void**)&qw_l, g_qw_l);
    cudaGetSymbolAddress((void**)&qr_h, g_qr_h); cudaGetSymbolAddress((void**)&qr_l, g_qr_l);
    cudaGetSymbolAddress((void**)&k_h,  g_k_h);  cudaGetSymbolAddress((void**)&k_l,  g_k_l);
    cudaGetSymbolAddress((void**)&rk_h, g_rk_h); cudaGetSymbolAddress((void**)&rk_l, g_rk_l);

    cudaFuncSetAttribute((const void*)mm_kernel<0>,  cudaFuncAttributeMaxDynamicSharedMemorySize, MM_SMEM);
    cudaFuncSetAttribute((const void*)mm_kernel<4>,  cudaFuncAttributeMaxDynamicSharedMemorySize, MM_SMEM);
    cudaFuncSetAttribute((const void*)mm_kernel<11>, cudaFuncAttributeMaxDynamicSharedMemorySize, MM_SMEM);
    cudaFuncSetAttribute((const void*)mm_kernel<5>,  cudaFuncAttributeMaxDynamicSharedMemorySize, MM_SMEM);
    cudaFuncSetAttribute((const void*)scores_mma_kernel, cudaFuncAttributeMaxDynamicSharedMemorySize, SC_SMEM);
    cudaFuncSetAttribute((const void*)pv_mma_kernel,  cudaFuncAttributeMaxDynamicSharedMemorySize, PV_SMEM);

    const dim3 wthr(32, 8);

    wconvT_kernel<<<dim3(D3 / 32, D / 32), wthr>>>(qkvw, qkvwT_h, qkvwT_l, D, D3);
    wconvT_kernel<<<dim3(D / 32,  D / 32), wthr>>>(rw,   rwT_h,   rwT_l,   D, D);
    wconvT_kernel<<<dim3(D / 32,  D / 32), wthr>>>(ow,   owT_h,   owT_l,   D, D);
    wconvT_kernel<<<dim3(DFF / 32, D / 32), wthr>>>(ffw1, w1T_h,  w1T_l,   D, DFF);
    wconvT_kernel<<<dim3(D / 32, DFF / 32), wthr>>>(ffw2, w2T_h,  w2T_l,   DFF, D);
    splitcvt_kernel<<<(T * D) / 1024, 256>>>(pos, pos_h, pos_l, T * D);

    ln_kernel<<<T, 256>>>(input, ln1g, ln1b, qin_h, qin_l);
    mm_kernel<0><<<dim3(D3 / 128, T / 128), 256, MM_SMEM>>>(
        qin_h, qin_l, qkvwT_h, qkvwT_l, nullptr, nullptr, wheads, nullptr, nullptr, T, D3, D);
    vconvT_kernel<<<dim3(T / 32, D / 32), wthr>>>(wheads, vt_h, vt_l);
    attnprep_kernel<<<(T * D) / 1024, 256>>>(wheads, rwb, rrb, qw_h, qw_l, qr_h, qr_l, k_h, k_l);
    mm_kernel<0><<<dim3(D / 128, T / 128), 256, MM_SMEM>>>(
        pos_h, pos_l, rwT_h, rwT_l, nullptr, nullptr, rk, nullptr, nullptr, T, D, D);
    splitcvt_kernel<<<(T * D) / 1024, 256>>>(rk, rk_h, rk_l, T * D);
    scores_mma_kernel<<<dim3(T / 128, T / 128, H), 256, SC_SMEM>>>(
        qw_h, qw_l, qr_h, qr_l, k_h, k_l, rk_h, rk_l, scores);
    softmax_kernel<<<dim3(T, H), 256>>>(scores, ph, pl);
    if ((long long)out_size >= (long long)T * D + (long long)H * T * T) {
        probs_out_kernel<<<dim3(T / 64, T), 256>>>(ph, pl, out + (size_t)T * D);
    }
    pv_mma_kernel<<<dim3(T / 128, H), 256, PV_SMEM>>>(ph, pl, vt_h, vt_l, av_h, av_l);
    mm_kernel<4><<<dim3(D / 128, T / 128), 256, MM_SMEM>>>(
        av_h, av_l, owT_h, owT_l, nullptr, input, x, nullptr, nullptr, T, D, D);
    ln_kernel<<<T, 256>>>(x, ln2g, ln2b, y_h, y_l);
    mm_kernel<11><<<dim3(DFF / 128, T / 128), 256, MM_SMEM>>>(
        y_h, y_l, w1T_h, w1T_l, ffb1, nullptr, nullptr, ff_h, ff_l, T, DFF, D);
    mm_kernel<5><<<dim3(D / 128, T / 128), 256, MM_SMEM>>>(
        ff_h, ff_l, w2T_h, w2T_l, ffb2, x, out, nullptr, nullptr, T, D, DFF);
}